// round 6
// baseline (speedup 1.0000x reference)
#include <cuda_runtime.h>
#include <cuda_bf16.h>
#include <math.h>
#include <stdint.h>

#define DD   248
#define HH   512
#define NMAX 10000
#define NNZMAX 4096

// ---------------- scratch (device globals; no allocs allowed) ----------------
__device__ float g_proj[NMAX * DD];
__device__ float g_S[NMAX * DD];
__device__ float g_h2[NMAX * DD];
__device__ __align__(16) __nv_bfloat16 g_fhi[NMAX * DD];
__device__ __align__(16) __nv_bfloat16 g_flo[NMAX * DD];
__device__ __align__(16) __nv_bfloat16 g_agghi[NMAX * DD];
__device__ __align__(16) __nv_bfloat16 g_agglo[NMAX * DD];
__device__ __align__(16) __nv_bfloat16 g_hidhi[NMAX * HH];
__device__ __align__(16) __nv_bfloat16 g_hidlo[NMAX * HH];
__device__ __align__(16) __nv_bfloat16 g_wmhi[DD * DD];
__device__ __align__(16) __nv_bfloat16 g_wmlo[DD * DD];
__device__ __align__(16) __nv_bfloat16 g_w1hi[HH * DD];
__device__ __align__(16) __nv_bfloat16 g_w1lo[HH * DD];
__device__ __align__(16) __nv_bfloat16 g_w2hi[DD * HH];
__device__ __align__(16) __nv_bfloat16 g_w2lo[DD * HH];
__device__ int   g_rowptr[DD + 1];
__device__ int   g_Is[NNZMAX];
__device__ int   g_Js[NNZMAX];
__device__ float g_Cs[NNZMAX];

// ---------------- fused prep: zero S + all bf16 splits ----------------
__device__ __forceinline__ void split1(const float* __restrict__ x,
                                       __nv_bfloat16* __restrict__ hi,
                                       __nv_bfloat16* __restrict__ lo, int i) {
    float v = x[i];
    __nv_bfloat16 h = __float2bfloat16(v);
    hi[i] = h;
    lo[i] = __float2bfloat16(v - __bfloat162float(h));
}

__global__ void prep_kernel(const float* __restrict__ F,
                            const float* __restrict__ Wmsg,
                            const float* __restrict__ W1,
                            const float* __restrict__ W2,
                            __nv_bfloat16* __restrict__ fhi, __nv_bfloat16* __restrict__ flo,
                            __nv_bfloat16* __restrict__ wmhi, __nv_bfloat16* __restrict__ wmlo,
                            __nv_bfloat16* __restrict__ w1hi, __nv_bfloat16* __restrict__ w1lo,
                            __nv_bfloat16* __restrict__ w2hi, __nv_bfloat16* __restrict__ w2lo,
                            float* __restrict__ S, int nfeat) {
    const int s0 = nfeat;
    const int s1 = DD * DD;
    const int s2 = HH * DD;
    const int s3 = DD * HH;
    int total = s0 + s1 + s2 + s3;
    int i = blockIdx.x * blockDim.x + threadIdx.x;
    int stride = gridDim.x * blockDim.x;
    for (; i < total; i += stride) {
        if (i < s0) {
            split1(F, fhi, flo, i);
            S[i] = 0.f;
        } else if (i < s0 + s1) {
            split1(Wmsg, wmhi, wmlo, i - s0);
        } else if (i < s0 + s1 + s2) {
            split1(W1, w1hi, w1lo, i - s0 - s1);
        } else {
            split1(W2, w2hi, w2lo, i - s0 - s1 - s2);
        }
    }
}

__global__ void build_csr_kernel(const int* __restrict__ Iv, const int* __restrict__ Jv,
                                 const int* __restrict__ Kv, const float* __restrict__ Cv,
                                 int nnz) {
    __shared__ int cnt[DD];
    __shared__ int off[DD + 1];
    int tid = threadIdx.x;
    for (int k = tid; k < DD; k += blockDim.x) cnt[k] = 0;
    __syncthreads();
    for (int t = tid; t < nnz; t += blockDim.x) atomicAdd(&cnt[Kv[t]], 1);
    __syncthreads();
    if (tid == 0) {
        int s = 0;
        for (int k = 0; k < DD; k++) { off[k] = s; s += cnt[k]; }
        off[DD] = s;
    }
    __syncthreads();
    for (int k = tid; k < DD; k += blockDim.x) {
        int pos = off[k];
        for (int t = 0; t < nnz; t++) {
            if (Kv[t] == k) {
                g_Is[pos] = Iv[t]; g_Js[pos] = Jv[t]; g_Cs[pos] = Cv[t];
                pos++;
            }
        }
    }
    for (int k = tid; k <= DD; k += blockDim.x) g_rowptr[k] = off[k];
}

// S[tgt[e]] += proj[src[e]] : 64 threads per edge, float4 vectorized atomics
__global__ void scatter_edges_kernel(const int* __restrict__ ei,
                                     const float* __restrict__ proj,
                                     float* __restrict__ S, int E) {
    int gid = blockIdx.x * blockDim.x + threadIdx.x;
    int e = gid >> 6;
    int c = gid & 63;
    if (e >= E || c >= DD / 4) return;
    int s = ei[e];
    int t = ei[E + e];
    float4 v = *(const float4*)(proj + (size_t)s * DD + c * 4);
#if __CUDA_ARCH__ >= 900
    atomicAdd((float4*)(S + (size_t)t * DD + c * 4), v);
#else
    float* p = S + (size_t)t * DD + c * 4;
    atomicAdd(p + 0, v.x); atomicAdd(p + 1, v.y);
    atomicAdd(p + 2, v.z); atomicAdd(p + 3, v.w);
#endif
}

// agg[n,k] = sum_t C_t * S[n,I_t] * f[n,J_t]; emits bf16 split directly
__global__ void bracket_kernel(const float* __restrict__ S, const float* __restrict__ F,
                               __nv_bfloat16* __restrict__ Ahi,
                               __nv_bfloat16* __restrict__ Alo) {
    __shared__ float sS[DD];
    __shared__ float sF[DD];
    int n = blockIdx.x;
    int tid = threadIdx.x;
    if (tid < DD) {
        sS[tid] = S[n * DD + tid];
        sF[tid] = F[n * DD + tid];
    }
    __syncthreads();
    if (tid < DD) {
        int b = g_rowptr[tid];
        int e = g_rowptr[tid + 1];
        float acc = 0.f;
        for (int t = b; t < e; t++)
            acc += g_Cs[t] * sS[g_Is[t]] * sF[g_Js[t]];
        __nv_bfloat16 h = __float2bfloat16(acc);
        Ahi[n * DD + tid] = h;
        Alo[n * DD + tid] = __float2bfloat16(acc - __bfloat162float(h));
    }
}

// ---------------- warp-MMA (mma.sync bf16) split GEMM v3 ----------------
// C[M,N] = A[M,K] @ B[N,K]^T via AhBh + AhBl + AlBh  (fp32 accumulate)
// CTA 128x128, 8 warps (4 M-groups x 2 N-groups), warp tile 32x64, BK=32,
// cp.async double buffer, ldmatrix frags, product-major MMA ordering.
#define MMA16816(c, a, b)                                                     \
    asm volatile(                                                             \
        "mma.sync.aligned.m16n8k16.row.col.f32.bf16.bf16.f32 "                \
        "{%0,%1,%2,%3},{%4,%5,%6,%7},{%8,%9},{%0,%1,%2,%3};"                  \
        : "+f"((c)[0]), "+f"((c)[1]), "+f"((c)[2]), "+f"((c)[3])              \
        : "r"((a)[0]), "r"((a)[1]), "r"((a)[2]), "r"((a)[3]),                 \
          "r"((b)[0]), "r"((b)[1]))

#define LDSM4(r0, r1, r2, r3, addr)                                           \
    asm volatile("ldmatrix.sync.aligned.m8n8.x4.shared.b16 {%0,%1,%2,%3}, [%4];" \
                 : "=r"(r0), "=r"(r1), "=r"(r2), "=r"(r3) : "r"(addr))

#define CPASYNC16(saddr, gaddr, sz)                                           \
    asm volatile("cp.async.cg.shared.global [%0], [%1], 16, %2;"              \
                 :: "r"(saddr), "l"(gaddr), "r"(sz) : "memory")

// per-buffer layout (bytes): Ah 128*80 | Al 128*80 | Bh 128*80 | Bl 128*80
#define ROWB      80u
#define APL       10240u
#define BOFF      20480u
#define BPL       10240u
#define BUF_BYTES 40960u

__device__ __forceinline__ uint32_t smem_u32(const void* p) {
    uint32_t a;
    asm("{ .reg .u64 t; cvta.to.shared.u64 t, %1; cvt.u32.u64 %0, t; }"
        : "=r"(a) : "l"(p));
    return a;
}

template <int ACT, int SPLIT_OUT>
__global__ __launch_bounds__(256, 2) void hmma_gemm(
    const __nv_bfloat16* __restrict__ Ah, const __nv_bfloat16* __restrict__ Al,
    const __nv_bfloat16* __restrict__ Bh, const __nv_bfloat16* __restrict__ Bl,
    const float* __restrict__ bias,
    float* __restrict__ Cf,
    __nv_bfloat16* __restrict__ Chi, __nv_bfloat16* __restrict__ Clo,
    int M, int N, int K)
{
    extern __shared__ char smem[];
    uint32_t sbase = smem_u32(smem);

    int tid = threadIdx.x;
    int wid = tid >> 5;
    int lane = tid & 31;
    int g = lane >> 2;
    int tg = lane & 3;
    int wm = wid >> 1;        // 0..3 (M, 32 rows each)
    int wn = wid & 1;         // 0..1 (N, 64 cols each)
    int m0 = blockIdx.x * 128;
    int n0 = blockIdx.y * 128;

    int lr = lane & 7;
    int lm01 = (lane >> 3) & 1;
    int lm23 = lane >> 4;

    float acc[2][8][4];
#pragma unroll
    for (int mi = 0; mi < 2; mi++)
#pragma unroll
        for (int ni = 0; ni < 8; ni++)
#pragma unroll
            for (int q = 0; q < 4; q++) acc[mi][ni][q] = 0.f;

    int nkc = (K + 31) >> 5;

    auto issue_chunk = [&](int c) {
        int kc = c << 5;
        uint32_t bufb = sbase + (uint32_t)(c & 1) * BUF_BYTES;
        // A: 1024 16B chunks (2 planes x 128 rows x 4 segs)
#pragma unroll
        for (int r = 0; r < 4; ++r) {
            int i = tid + (r << 8);
            int plane = i >> 9;
            int row = (i >> 2) & 127;
            int seg = i & 3;
            int gm = m0 + row;
            int k = kc + seg * 8;
            const __nv_bfloat16* src = (plane ? Al : Ah) + (size_t)gm * K + k;
            uint32_t dst = bufb + (uint32_t)plane * APL + (uint32_t)row * ROWB
                           + (uint32_t)seg * 16u;
            uint32_t sz = (gm < M && k < K) ? 16u : 0u;
            CPASYNC16(dst, src, sz);
        }
        // B: 1024 16B chunks (2 planes x 128 rows x 4 segs)
#pragma unroll
        for (int r = 0; r < 4; ++r) {
            int j = tid + (r << 8);
            int plane = j >> 9;
            int row = (j >> 2) & 127;
            int seg = j & 3;
            int gn = n0 + row;
            int k = kc + seg * 8;
            const __nv_bfloat16* src = (plane ? Bl : Bh) + (size_t)gn * K + k;
            uint32_t dst = bufb + BOFF + (uint32_t)plane * BPL
                           + (uint32_t)row * ROWB + (uint32_t)seg * 16u;
            uint32_t sz = (gn < N && k < K) ? 16u : 0u;
            CPASYNC16(dst, src, sz);
        }
        asm volatile("cp.async.commit_group;" ::: "memory");
    };

    issue_chunk(0);

    for (int c = 0; c < nkc; ++c) {
        if (c + 1 < nkc) {
            issue_chunk(c + 1);
            asm volatile("cp.async.wait_group 1;" ::: "memory");
        } else {
            asm volatile("cp.async.wait_group 0;" ::: "memory");
        }
        __syncthreads();

        uint32_t abase = sbase + (uint32_t)(c & 1) * BUF_BYTES;
        uint32_t bbase = abase + BOFF;
#pragma unroll
        for (int ks = 0; ks < 32; ks += 16) {
            uint32_t ah[2][4], al[2][4], bh[8][2], bl[8][2];
#pragma unroll
            for (int mi = 0; mi < 2; mi++) {
                uint32_t row = (uint32_t)(wm * 32 + mi * 16 + lm01 * 8 + lr);
                uint32_t col = (uint32_t)(ks + lm23 * 8);
                uint32_t off = row * ROWB + col * 2u;
                LDSM4(ah[mi][0], ah[mi][1], ah[mi][2], ah[mi][3], abase + off);
                LDSM4(al[mi][0], al[mi][1], al[mi][2], al[mi][3],
                      abase + APL + off);
            }
#pragma unroll
            for (int ng = 0; ng < 4; ng++) {
                uint32_t row = (uint32_t)(wn * 64 + ng * 16 + lm23 * 8 + lr);
                uint32_t col = (uint32_t)(ks + lm01 * 8);
                uint32_t off = row * ROWB + col * 2u;
                LDSM4(bh[2 * ng][0], bh[2 * ng][1], bh[2 * ng + 1][0],
                      bh[2 * ng + 1][1], bbase + off);
                LDSM4(bl[2 * ng][0], bl[2 * ng][1], bl[2 * ng + 1][0],
                      bl[2 * ng + 1][1], bbase + BPL + off);
            }
            // product-major ordering: same accumulator revisited only every 16 MMAs
#pragma unroll
            for (int mi = 0; mi < 2; mi++)
#pragma unroll
                for (int ni = 0; ni < 8; ni++)
                    MMA16816(acc[mi][ni], ah[mi], bh[ni]);
#pragma unroll
            for (int mi = 0; mi < 2; mi++)
#pragma unroll
                for (int ni = 0; ni < 8; ni++)
                    MMA16816(acc[mi][ni], ah[mi], bl[ni]);
#pragma unroll
            for (int mi = 0; mi < 2; mi++)
#pragma unroll
                for (int ni = 0; ni < 8; ni++)
                    MMA16816(acc[mi][ni], al[mi], bh[ni]);
        }
        __syncthreads();
    }

    // ---- epilogue ----
#pragma unroll
    for (int mi = 0; mi < 2; mi++) {
#pragma unroll
        for (int ni = 0; ni < 8; ni++) {
#pragma unroll
            for (int h = 0; h < 2; h++) {
                int gm = m0 + wm * 32 + mi * 16 + g + h * 8;
                if (gm >= M) continue;
#pragma unroll
                for (int q = 0; q < 2; q++) {
                    int gn = n0 + wn * 64 + ni * 8 + tg * 2 + q;
                    if (gn >= N) continue;
                    float v = acc[mi][ni][h * 2 + q];
                    if (bias) v += bias[gn];
                    if (ACT == 1) v = v / (1.f + expf(-v));
                    if (SPLIT_OUT == 1) {
                        __nv_bfloat16 hh = __float2bfloat16(v);
                        Chi[(size_t)gm * N + gn] = hh;
                        Clo[(size_t)gm * N + gn] =
                            __float2bfloat16(v - __bfloat162float(hh));
                    } else {
                        Cf[(size_t)gm * N + gn] = v;
                    }
                }
            }
        }
    }
}

// ---------------- residual + LayerNorm ----------------
__global__ void ln_kernel(const float* __restrict__ F, const float* __restrict__ h2,
                          const float* __restrict__ gamma, const float* __restrict__ beta,
                          float* __restrict__ out) {
    __shared__ float red[256];
    int n = blockIdx.x;
    int tid = threadIdx.x;
    float x = (tid < DD) ? (F[n * DD + tid] + h2[n * DD + tid]) : 0.f;
    red[tid] = x;
    __syncthreads();
#pragma unroll
    for (int s = 128; s > 0; s >>= 1) {
        if (tid < s) red[tid] += red[tid + s];
        __syncthreads();
    }
    float mu = red[0] * (1.f / DD);
    __syncthreads();
    float xc = (tid < DD) ? (x - mu) : 0.f;
    red[tid] = xc * xc;
    __syncthreads();
#pragma unroll
    for (int s = 128; s > 0; s >>= 1) {
        if (tid < s) red[tid] += red[tid + s];
        __syncthreads();
    }
    float var = red[0] * (1.f / DD);
    float r = rsqrtf(var + 1e-5f);
    if (tid < DD)
        out[n * DD + tid] = xc * r * gamma[tid] + beta[tid];
}

// ---------------- launcher ----------------
extern "C" void kernel_launch(void* const* d_in, const int* in_sizes, int n_in,
                              void* d_out, int out_size) {
    const float* features = (const float*)d_in[0];
    const int*   ei       = (const int*)d_in[1];
    const float* Wmsg     = (const float*)d_in[2];
    const float* W1       = (const float*)d_in[3];
    const float* b1       = (const float*)d_in[4];
    const float* W2       = (const float*)d_in[5];
    const float* b2       = (const float*)d_in[6];
    const float* gamma    = (const float*)d_in[7];
    const float* beta     = (const float*)d_in[8];
    const int*   Iv       = (const int*)d_in[9];
    const int*   Jv       = (const int*)d_in[10];
    const int*   Kv       = (const int*)d_in[11];
    const float* Cv       = (const float*)d_in[12];
    float* out = (float*)d_out;

    int N   = in_sizes[0] / DD;
    int E   = in_sizes[1] / 2;
    int nnz = in_sizes[9];

    float *p_proj, *p_S, *p_h2;
    __nv_bfloat16 *p_fhi, *p_flo, *p_agghi, *p_agglo, *p_hidhi, *p_hidlo;
    __nv_bfloat16 *p_wmhi, *p_wmlo, *p_w1hi, *p_w1lo, *p_w2hi, *p_w2lo;
    cudaGetSymbolAddress((void**)&p_proj,  g_proj);
    cudaGetSymbolAddress((void**)&p_S,     g_S);
    cudaGetSymbolAddress((void**)&p_h2,    g_h2);
    cudaGetSymbolAddress((void**)&p_fhi,   g_fhi);
    cudaGetSymbolAddress((void**)&p_flo,   g_flo);
    cudaGetSymbolAddress((void**)&p_agghi, g_agghi);
    cudaGetSymbolAddress((void**)&p_agglo, g_agglo);
    cudaGetSymbolAddress((void**)&p_hidhi, g_hidhi);
    cudaGetSymbolAddress((void**)&p_hidlo, g_hidlo);
    cudaGetSymbolAddress((void**)&p_wmhi,  g_wmhi);
    cudaGetSymbolAddress((void**)&p_wmlo,  g_wmlo);
    cudaGetSymbolAddress((void**)&p_w1hi,  g_w1hi);
    cudaGetSymbolAddress((void**)&p_w1lo,  g_w1lo);
    cudaGetSymbolAddress((void**)&p_w2hi,  g_w2hi);
    cudaGetSymbolAddress((void**)&p_w2lo,  g_w2lo);

    const int SMEM_SZ = 2 * 40960;
    cudaFuncSetAttribute(hmma_gemm<0, 0>, cudaFuncAttributeMaxDynamicSharedMemorySize, SMEM_SZ);
    cudaFuncSetAttribute(hmma_gemm<1, 1>, cudaFuncAttributeMaxDynamicSharedMemorySize, SMEM_SZ);

    // fused: zero S + bf16 splits of features and all weights
    prep_kernel<<<512, 256>>>(features, Wmsg, W1, W2,
                              p_fhi, p_flo, p_wmhi, p_wmlo,
                              p_w1hi, p_w1lo, p_w2hi, p_w2lo,
                              p_S, N * DD);

    // deterministic CSR of structure constants by output index K
    build_csr_kernel<<<1, 256>>>(Iv, Jv, Kv, Cv, nnz);

    int mtiles = (N + 127) / 128;

    // proj = features @ Wmsg^T   (fp32 out)
    hmma_gemm<0, 0><<<dim3(mtiles, (DD + 127) / 128), 256, SMEM_SZ>>>(
        p_fhi, p_flo, p_wmhi, p_wmlo, nullptr, p_proj, nullptr, nullptr, N, DD, DD);

    // S[tgt] += proj[src]  (vectorized atomics, 64 thr/edge)
    scatter_edges_kernel<<<(E * 64 + 255) / 256, 256>>>(ei, p_proj, p_S, E);

    // agg = bracket(S, features), emitted pre-split
    bracket_kernel<<<N, 256>>>(p_S, features, p_agghi, p_agglo);

    // hidden = silu(agg @ W1^T + b1), emitted pre-split
    hmma_gemm<1, 1><<<dim3(mtiles, (HH + 127) / 128), 256, SMEM_SZ>>>(
        p_agghi, p_agglo, p_w1hi, p_w1lo, b1, nullptr, p_hidhi, p_hidlo, N, HH, DD);

    // h2 = hidden @ W2^T + b2   (fp32 out)
    hmma_gemm<0, 0><<<dim3(mtiles, (DD + 127) / 128), 256, SMEM_SZ>>>(
        p_hidhi, p_hidlo, p_w2hi, p_w2lo, b2, p_h2, nullptr, nullptr, N, DD, HH);

    // out = LayerNorm(features + h2)
    ln_kernel<<<N, 256>>>(features, p_h2, gamma, beta, out);
}

// round 7
// speedup vs baseline: 1.0337x; 1.0337x over previous
#include <cuda_runtime.h>
#include <cuda_bf16.h>
#include <math.h>
#include <stdint.h>

#define DD   248
#define HH   512
#define NMAX 10000
#define NNZMAX 4096

// ---------------- scratch (device globals; no allocs allowed) ----------------
__device__ float g_proj[NMAX * DD];
__device__ float g_S[NMAX * DD];
__device__ float g_h2[NMAX * DD];
__device__ __align__(16) __nv_bfloat16 g_fhi[NMAX * DD];
__device__ __align__(16) __nv_bfloat16 g_flo[NMAX * DD];
__device__ __align__(16) __nv_bfloat16 g_agghi[NMAX * DD];
__device__ __align__(16) __nv_bfloat16 g_agglo[NMAX * DD];
__device__ __align__(16) __nv_bfloat16 g_hidhi[NMAX * HH];
__device__ __align__(16) __nv_bfloat16 g_hidlo[NMAX * HH];
__device__ __align__(16) __nv_bfloat16 g_wmhi[DD * DD];
__device__ __align__(16) __nv_bfloat16 g_wmlo[DD * DD];
__device__ __align__(16) __nv_bfloat16 g_w1hi[HH * DD];
__device__ __align__(16) __nv_bfloat16 g_w1lo[HH * DD];
__device__ __align__(16) __nv_bfloat16 g_w2hi[DD * HH];
__device__ __align__(16) __nv_bfloat16 g_w2lo[DD * HH];
__device__ int   g_rowptr[DD + 1];
__device__ int   g_Is[NNZMAX];
__device__ int   g_Js[NNZMAX];
__device__ float g_Cs[NNZMAX];

// ---------------- fused prep: zero S + all bf16 splits ----------------
__device__ __forceinline__ void split1(const float* __restrict__ x,
                                       __nv_bfloat16* __restrict__ hi,
                                       __nv_bfloat16* __restrict__ lo, int i) {
    float v = x[i];
    __nv_bfloat16 h = __float2bfloat16(v);
    hi[i] = h;
    lo[i] = __float2bfloat16(v - __bfloat162float(h));
}

__global__ void prep_kernel(const float* __restrict__ F,
                            const float* __restrict__ Wmsg,
                            const float* __restrict__ W1,
                            const float* __restrict__ W2,
                            __nv_bfloat16* __restrict__ fhi, __nv_bfloat16* __restrict__ flo,
                            __nv_bfloat16* __restrict__ wmhi, __nv_bfloat16* __restrict__ wmlo,
                            __nv_bfloat16* __restrict__ w1hi, __nv_bfloat16* __restrict__ w1lo,
                            __nv_bfloat16* __restrict__ w2hi, __nv_bfloat16* __restrict__ w2lo,
                            float* __restrict__ S, int nfeat) {
    const int s0 = nfeat;
    const int s1 = DD * DD;
    const int s2 = HH * DD;
    const int s3 = DD * HH;
    int total = s0 + s1 + s2 + s3;
    int i = blockIdx.x * blockDim.x + threadIdx.x;
    int stride = gridDim.x * blockDim.x;
    for (; i < total; i += stride) {
        if (i < s0) {
            split1(F, fhi, flo, i);
            S[i] = 0.f;
        } else if (i < s0 + s1) {
            split1(Wmsg, wmhi, wmlo, i - s0);
        } else if (i < s0 + s1 + s2) {
            split1(W1, w1hi, w1lo, i - s0 - s1);
        } else {
            split1(W2, w2hi, w2lo, i - s0 - s1 - s2);
        }
    }
}

__global__ void build_csr_kernel(const int* __restrict__ Iv, const int* __restrict__ Jv,
                                 const int* __restrict__ Kv, const float* __restrict__ Cv,
                                 int nnz) {
    __shared__ int cnt[DD];
    __shared__ int off[DD + 1];
    int tid = threadIdx.x;
    for (int k = tid; k < DD; k += blockDim.x) cnt[k] = 0;
    __syncthreads();
    for (int t = tid; t < nnz; t += blockDim.x) atomicAdd(&cnt[Kv[t]], 1);
    __syncthreads();
    if (tid == 0) {
        int s = 0;
        for (int k = 0; k < DD; k++) { off[k] = s; s += cnt[k]; }
        off[DD] = s;
    }
    __syncthreads();
    for (int k = tid; k < DD; k += blockDim.x) {
        int pos = off[k];
        for (int t = 0; t < nnz; t++) {
            if (Kv[t] == k) {
                g_Is[pos] = Iv[t]; g_Js[pos] = Jv[t]; g_Cs[pos] = Cv[t];
                pos++;
            }
        }
    }
    for (int k = tid; k <= DD; k += blockDim.x) g_rowptr[k] = off[k];
}

// S[tgt[e]] += proj[src[e]] : 64 threads per edge, float4 vectorized atomics
__global__ void scatter_edges_kernel(const int* __restrict__ ei,
                                     const float* __restrict__ proj,
                                     float* __restrict__ S, int E) {
    int gid = blockIdx.x * blockDim.x + threadIdx.x;
    int e = gid >> 6;
    int c = gid & 63;
    if (e >= E || c >= DD / 4) return;
    int s = ei[e];
    int t = ei[E + e];
    float4 v = *(const float4*)(proj + (size_t)s * DD + c * 4);
#if __CUDA_ARCH__ >= 900
    atomicAdd((float4*)(S + (size_t)t * DD + c * 4), v);
#else
    float* p = S + (size_t)t * DD + c * 4;
    atomicAdd(p + 0, v.x); atomicAdd(p + 1, v.y);
    atomicAdd(p + 2, v.z); atomicAdd(p + 3, v.w);
#endif
}

// agg[n,k] = sum_t C_t * S[n,I_t] * f[n,J_t]; emits bf16 split directly
__global__ void bracket_kernel(const float* __restrict__ S, const float* __restrict__ F,
                               __nv_bfloat16* __restrict__ Ahi,
                               __nv_bfloat16* __restrict__ Alo) {
    __shared__ float sS[DD];
    __shared__ float sF[DD];
    int n = blockIdx.x;
    int tid = threadIdx.x;
    if (tid < DD) {
        sS[tid] = S[n * DD + tid];
        sF[tid] = F[n * DD + tid];
    }
    __syncthreads();
    if (tid < DD) {
        int b = g_rowptr[tid];
        int e = g_rowptr[tid + 1];
        float acc = 0.f;
        for (int t = b; t < e; t++)
            acc += g_Cs[t] * sS[g_Is[t]] * sF[g_Js[t]];
        __nv_bfloat16 h = __float2bfloat16(acc);
        Ahi[n * DD + tid] = h;
        Alo[n * DD + tid] = __float2bfloat16(acc - __bfloat162float(h));
    }
}

// ---------------- warp-MMA (mma.sync bf16) split GEMM (R5 config + 3-stage) ----
// C[M,N] = A[M,K] @ B[N,K]^T via AhBh + AhBl + AlBh  (fp32 accumulate)
// CTA 128x64, 8 warps 4x2, warp tile 32x32, BK=32, cp.async 3-stage pipeline,
// ldmatrix fragment loads. Smem rows padded to 40 elems (80B, conflict-free).
#define MMA16816(c, a, b)                                                     \
    asm volatile(                                                             \
        "mma.sync.aligned.m16n8k16.row.col.f32.bf16.bf16.f32 "                \
        "{%0,%1,%2,%3},{%4,%5,%6,%7},{%8,%9},{%0,%1,%2,%3};"                  \
        : "+f"((c)[0]), "+f"((c)[1]), "+f"((c)[2]), "+f"((c)[3])              \
        : "r"((a)[0]), "r"((a)[1]), "r"((a)[2]), "r"((a)[3]),                 \
          "r"((b)[0]), "r"((b)[1]))

#define LDSM4(r0, r1, r2, r3, addr)                                           \
    asm volatile("ldmatrix.sync.aligned.m8n8.x4.shared.b16 {%0,%1,%2,%3}, [%4];" \
                 : "=r"(r0), "=r"(r1), "=r"(r2), "=r"(r3) : "r"(addr))

#define CPASYNC16(saddr, gaddr, sz)                                           \
    asm volatile("cp.async.cg.shared.global [%0], [%1], 16, %2;"              \
                 :: "r"(saddr), "l"(gaddr), "r"(sz) : "memory")

// per-buffer layout (bytes): Ah 128*80 | Al 128*80 | Bh 64*80 | Bl 64*80
#define BUF_BYTES   30720u
#define A_PLANE     10240u
#define B_OFF       20480u
#define B_PLANE     5120u
#define ROWB        80u
#define NSTAGE      3

__device__ __forceinline__ uint32_t smem_u32(const void* p) {
    uint32_t a;
    asm("{ .reg .u64 t; cvta.to.shared.u64 t, %1; cvt.u32.u64 %0, t; }"
        : "=r"(a) : "l"(p));
    return a;
}

template <int ACT, int SPLIT_OUT>
__global__ __launch_bounds__(256) void hmma_gemm(
    const __nv_bfloat16* __restrict__ Ah, const __nv_bfloat16* __restrict__ Al,
    const __nv_bfloat16* __restrict__ Bh, const __nv_bfloat16* __restrict__ Bl,
    const float* __restrict__ bias,
    float* __restrict__ Cf,
    __nv_bfloat16* __restrict__ Chi, __nv_bfloat16* __restrict__ Clo,
    int M, int N, int K)
{
    extern __shared__ char smem[];
    uint32_t sbase = smem_u32(smem);

    int tid = threadIdx.x;
    int wid = tid >> 5;
    int lane = tid & 31;
    int g = lane >> 2;
    int tg = lane & 3;
    int wm = wid >> 1;
    int wn = wid & 1;
    int m0 = blockIdx.x * 128;
    int n0 = blockIdx.y * 64;

    int lr = lane & 7;
    int lm01 = (lane >> 3) & 1;
    int lm23 = lane >> 4;

    float acc[2][4][4];
#pragma unroll
    for (int mi = 0; mi < 2; mi++)
#pragma unroll
        for (int ni = 0; ni < 4; ni++)
#pragma unroll
            for (int q = 0; q < 4; q++) acc[mi][ni][q] = 0.f;

    int nkc = (K + 31) >> 5;

    auto issue_chunk = [&](int c) {
        int kc = c << 5;
        uint32_t bufb = sbase + (uint32_t)(c % NSTAGE) * BUF_BYTES;
#pragma unroll
        for (int r = 0; r < 4; ++r) {
            int i = tid + (r << 8);
            int plane = i >> 9;
            int row = (i >> 2) & 127;
            int seg = i & 3;
            int gm = m0 + row;
            int k = kc + seg * 8;
            const __nv_bfloat16* src = (plane ? Al : Ah) + (size_t)gm * K + k;
            uint32_t dst = bufb + (uint32_t)plane * A_PLANE + (uint32_t)row * ROWB
                           + (uint32_t)seg * 16u;
            uint32_t sz = (gm < M && k < K) ? 16u : 0u;
            CPASYNC16(dst, src, sz);
        }
#pragma unroll
        for (int r = 0; r < 2; ++r) {
            int i = tid + (r << 8);
            int plane = i >> 8;
            int row = (i >> 2) & 63;
            int seg = i & 3;
            int gn = n0 + row;
            int k = kc + seg * 8;
            const __nv_bfloat16* src = (plane ? Bl : Bh) + (size_t)gn * K + k;
            uint32_t dst = bufb + B_OFF + (uint32_t)plane * B_PLANE
                           + (uint32_t)row * ROWB + (uint32_t)seg * 16u;
            uint32_t sz = (gn < N && k < K) ? 16u : 0u;
            CPASYNC16(dst, src, sz);
        }
        asm volatile("cp.async.commit_group;" ::: "memory");
    };

    issue_chunk(0);
    if (nkc > 1) issue_chunk(1);

    for (int c = 0; c < nkc; ++c) {
        if (c + 2 < nkc) {
            issue_chunk(c + 2);
            asm volatile("cp.async.wait_group 2;" ::: "memory");
        } else if (c + 1 < nkc) {
            asm volatile("cp.async.wait_group 1;" ::: "memory");
        } else {
            asm volatile("cp.async.wait_group 0;" ::: "memory");
        }
        __syncthreads();

        uint32_t abase = sbase + (uint32_t)(c % NSTAGE) * BUF_BYTES;
        uint32_t bbase = abase + B_OFF;
#pragma unroll
        for (int ks = 0; ks < 32; ks += 16) {
            uint32_t ah[2][4], al[2][4], bh[4][2], bl[4][2];
#pragma unroll
            for (int mi = 0; mi < 2; mi++) {
                uint32_t row = (uint32_t)(wm * 32 + mi * 16 + lm01 * 8 + lr);
                uint32_t col = (uint32_t)(ks + lm23 * 8);
                uint32_t off = row * ROWB + col * 2u;
                LDSM4(ah[mi][0], ah[mi][1], ah[mi][2], ah[mi][3], abase + off);
                LDSM4(al[mi][0], al[mi][1], al[mi][2], al[mi][3],
                      abase + A_PLANE + off);
            }
#pragma unroll
            for (int ng = 0; ng < 2; ng++) {
                uint32_t row = (uint32_t)(wn * 32 + ng * 16 + lm23 * 8 + lr);
                uint32_t col = (uint32_t)(ks + lm01 * 8);
                uint32_t off = row * ROWB + col * 2u;
                LDSM4(bh[2 * ng][0], bh[2 * ng][1], bh[2 * ng + 1][0],
                      bh[2 * ng + 1][1], bbase + off);
                LDSM4(bl[2 * ng][0], bl[2 * ng][1], bl[2 * ng + 1][0],
                      bl[2 * ng + 1][1], bbase + B_PLANE + off);
            }
#pragma unroll
            for (int mi = 0; mi < 2; mi++)
#pragma unroll
                for (int ni = 0; ni < 4; ni++) {
                    MMA16816(acc[mi][ni], ah[mi], bh[ni]);
                    MMA16816(acc[mi][ni], ah[mi], bl[ni]);
                    MMA16816(acc[mi][ni], al[mi], bh[ni]);
                }
        }
        __syncthreads();
    }

    // ---- epilogue ----
#pragma unroll
    for (int mi = 0; mi < 2; mi++) {
#pragma unroll
        for (int ni = 0; ni < 4; ni++) {
#pragma unroll
            for (int h = 0; h < 2; h++) {
                int gm = m0 + wm * 32 + mi * 16 + g + h * 8;
                if (gm >= M) continue;
#pragma unroll
                for (int q = 0; q < 2; q++) {
                    int gn = n0 + wn * 32 + ni * 8 + tg * 2 + q;
                    if (gn >= N) continue;
                    float v = acc[mi][ni][h * 2 + q];
                    if (bias) v += bias[gn];
                    if (ACT == 1) v = v / (1.f + expf(-v));
                    if (SPLIT_OUT == 1) {
                        __nv_bfloat16 hh = __float2bfloat16(v);
                        Chi[(size_t)gm * N + gn] = hh;
                        Clo[(size_t)gm * N + gn] =
                            __float2bfloat16(v - __bfloat162float(hh));
                    } else {
                        Cf[(size_t)gm * N + gn] = v;
                    }
                }
            }
        }
    }
}

// ---------------- residual + LayerNorm ----------------
__global__ void ln_kernel(const float* __restrict__ F, const float* __restrict__ h2,
                          const float* __restrict__ gamma, const float* __restrict__ beta,
                          float* __restrict__ out) {
    __shared__ float red[256];
    int n = blockIdx.x;
    int tid = threadIdx.x;
    float x = (tid < DD) ? (F[n * DD + tid] + h2[n * DD + tid]) : 0.f;
    red[tid] = x;
    __syncthreads();
#pragma unroll
    for (int s = 128; s > 0; s >>= 1) {
        if (tid < s) red[tid] += red[tid + s];
        __syncthreads();
    }
    float mu = red[0] * (1.f / DD);
    __syncthreads();
    float xc = (tid < DD) ? (x - mu) : 0.f;
    red[tid] = xc * xc;
    __syncthreads();
#pragma unroll
    for (int s = 128; s > 0; s >>= 1) {
        if (tid < s) red[tid] += red[tid + s];
        __syncthreads();
    }
    float var = red[0] * (1.f / DD);
    float r = rsqrtf(var + 1e-5f);
    if (tid < DD)
        out[n * DD + tid] = xc * r * gamma[tid] + beta[tid];
}

// ---------------- launcher ----------------
extern "C" void kernel_launch(void* const* d_in, const int* in_sizes, int n_in,
                              void* d_out, int out_size) {
    const float* features = (const float*)d_in[0];
    const int*   ei       = (const int*)d_in[1];
    const float* Wmsg     = (const float*)d_in[2];
    const float* W1       = (const float*)d_in[3];
    const float* b1       = (const float*)d_in[4];
    const float* W2       = (const float*)d_in[5];
    const float* b2       = (const float*)d_in[6];
    const float* gamma    = (const float*)d_in[7];
    const float* beta     = (const float*)d_in[8];
    const int*   Iv       = (const int*)d_in[9];
    const int*   Jv       = (const int*)d_in[10];
    const int*   Kv       = (const int*)d_in[11];
    const float* Cv       = (const float*)d_in[12];
    float* out = (float*)d_out;

    int N   = in_sizes[0] / DD;
    int E   = in_sizes[1] / 2;
    int nnz = in_sizes[9];

    float *p_proj, *p_S, *p_h2;
    __nv_bfloat16 *p_fhi, *p_flo, *p_agghi, *p_agglo, *p_hidhi, *p_hidlo;
    __nv_bfloat16 *p_wmhi, *p_wmlo, *p_w1hi, *p_w1lo, *p_w2hi, *p_w2lo;
    cudaGetSymbolAddress((void**)&p_proj,  g_proj);
    cudaGetSymbolAddress((void**)&p_S,     g_S);
    cudaGetSymbolAddress((void**)&p_h2,    g_h2);
    cudaGetSymbolAddress((void**)&p_fhi,   g_fhi);
    cudaGetSymbolAddress((void**)&p_flo,   g_flo);
    cudaGetSymbolAddress((void**)&p_agghi, g_agghi);
    cudaGetSymbolAddress((void**)&p_agglo, g_agglo);
    cudaGetSymbolAddress((void**)&p_hidhi, g_hidhi);
    cudaGetSymbolAddress((void**)&p_hidlo, g_hidlo);
    cudaGetSymbolAddress((void**)&p_wmhi,  g_wmhi);
    cudaGetSymbolAddress((void**)&p_wmlo,  g_wmlo);
    cudaGetSymbolAddress((void**)&p_w1hi,  g_w1hi);
    cudaGetSymbolAddress((void**)&p_w1lo,  g_w1lo);
    cudaGetSymbolAddress((void**)&p_w2hi,  g_w2hi);
    cudaGetSymbolAddress((void**)&p_w2lo,  g_w2lo);

    const int SMEM_SZ = NSTAGE * 30720;
    cudaFuncSetAttribute(hmma_gemm<0, 0>, cudaFuncAttributeMaxDynamicSharedMemorySize, SMEM_SZ);
    cudaFuncSetAttribute(hmma_gemm<1, 1>, cudaFuncAttributeMaxDynamicSharedMemorySize, SMEM_SZ);

    // fused: zero S + bf16 splits of features and all weights
    prep_kernel<<<512, 256>>>(features, Wmsg, W1, W2,
                              p_fhi, p_flo, p_wmhi, p_wmlo,
                              p_w1hi, p_w1lo, p_w2hi, p_w2lo,
                              p_S, N * DD);

    // deterministic CSR of structure constants by output index K
    build_csr_kernel<<<1, 256>>>(Iv, Jv, Kv, Cv, nnz);

    int mtiles = (N + 127) / 128;

    // proj = features @ Wmsg^T   (fp32 out)
    hmma_gemm<0, 0><<<dim3(mtiles, (DD + 63) / 64), 256, SMEM_SZ>>>(
        p_fhi, p_flo, p_wmhi, p_wmlo, nullptr, p_proj, nullptr, nullptr, N, DD, DD);

    // S[tgt] += proj[src]  (vectorized atomics, 64 thr/edge)
    scatter_edges_kernel<<<(E * 64 + 255) / 256, 256>>>(ei, p_proj, p_S, E);

    // agg = bracket(S, features), emitted pre-split
    bracket_kernel<<<N, 256>>>(p_S, features, p_agghi, p_agglo);

    // hidden = silu(agg @ W1^T + b1), emitted pre-split
    hmma_gemm<1, 1><<<dim3(mtiles, (HH + 63) / 64), 256, SMEM_SZ>>>(
        p_agghi, p_agglo, p_w1hi, p_w1lo, b1, nullptr, p_hidhi, p_hidlo, N, HH, DD);

    // h2 = hidden @ W2^T + b2   (fp32 out)
    hmma_gemm<0, 0><<<dim3(mtiles, (DD + 63) / 64), 256, SMEM_SZ>>>(
        p_hidhi, p_hidlo, p_w2hi, p_w2lo, b2, p_h2, nullptr, nullptr, N, DD, HH);

    // out = LayerNorm(features + h2)
    ln_kernel<<<N, 256>>>(features, p_h2, gamma, beta, out);
}

// round 8
// speedup vs baseline: 1.6139x; 1.5612x over previous
#include <cuda_runtime.h>
#include <cuda_bf16.h>
#include <math.h>
#include <stdint.h>

#define DD   248
#define HH   512
#define NMAX 10000
#define NNZMAX 4096

// ---------------- scratch (device globals; no allocs allowed) ----------------
__device__ float g_proj[NMAX * DD];
__device__ float g_S[NMAX * DD];
__device__ float g_h2[NMAX * DD];
__device__ __align__(16) __nv_bfloat16 g_fhi[NMAX * DD];
__device__ __align__(16) __nv_bfloat16 g_flo[NMAX * DD];
__device__ __align__(16) __nv_bfloat16 g_agghi[NMAX * DD];
__device__ __align__(16) __nv_bfloat16 g_agglo[NMAX * DD];
__device__ __align__(16) __nv_bfloat16 g_hidhi[NMAX * HH];
__device__ __align__(16) __nv_bfloat16 g_hidlo[NMAX * HH];
__device__ __align__(16) __nv_bfloat16 g_wmhi[DD * DD];
__device__ __align__(16) __nv_bfloat16 g_wmlo[DD * DD];
__device__ __align__(16) __nv_bfloat16 g_w1hi[HH * DD];
__device__ __align__(16) __nv_bfloat16 g_w1lo[HH * DD];
__device__ __align__(16) __nv_bfloat16 g_w2hi[DD * HH];
__device__ __align__(16) __nv_bfloat16 g_w2lo[DD * HH];
__device__ int   g_rowptr[DD + 1];
__device__ int   g_Is[NNZMAX];
__device__ int   g_Js[NNZMAX];
__device__ float g_Cs[NNZMAX];

// ---------------- splits ----------------
__device__ __forceinline__ void split1(const float* __restrict__ x,
                                       __nv_bfloat16* __restrict__ hi,
                                       __nv_bfloat16* __restrict__ lo, int i) {
    float v = x[i];
    __nv_bfloat16 h = __float2bfloat16(v);
    hi[i] = h;
    lo[i] = __float2bfloat16(v - __bfloat162float(h));
}

// launch #1: features split + zero S
__global__ void prep_feat_kernel(const float* __restrict__ F,
                                 __nv_bfloat16* __restrict__ fhi,
                                 __nv_bfloat16* __restrict__ flo,
                                 float* __restrict__ S, int nfeat) {
    int i = blockIdx.x * blockDim.x + threadIdx.x;
    int stride = gridDim.x * blockDim.x;
    for (; i < nfeat; i += stride) {
        split1(F, fhi, flo, i);
        S[i] = 0.f;
    }
}

// launch #2: all weight splits
__global__ void prep_w_kernel(const float* __restrict__ Wmsg,
                              const float* __restrict__ W1,
                              const float* __restrict__ W2,
                              __nv_bfloat16* __restrict__ wmhi, __nv_bfloat16* __restrict__ wmlo,
                              __nv_bfloat16* __restrict__ w1hi, __nv_bfloat16* __restrict__ w1lo,
                              __nv_bfloat16* __restrict__ w2hi, __nv_bfloat16* __restrict__ w2lo) {
    const int s1 = DD * DD;
    const int s2 = HH * DD;
    const int s3 = DD * HH;
    int total = s1 + s2 + s3;
    int i = blockIdx.x * blockDim.x + threadIdx.x;
    int stride = gridDim.x * blockDim.x;
    for (; i < total; i += stride) {
        if (i < s1)            split1(Wmsg, wmhi, wmlo, i);
        else if (i < s1 + s2)  split1(W1, w1hi, w1lo, i - s1);
        else                   split1(W2, w2hi, w2lo, i - s1 - s2);
    }
}

// launch #3: deterministic parallel CSR build (stable rank-by-scan).
// Each block caches Kv in smem, computes counts+offsets locally, then each of
// its 256 owned triples finds its exact stable position.
__global__ void build_csr_fast(const int* __restrict__ Iv, const int* __restrict__ Jv,
                               const int* __restrict__ Kv, const float* __restrict__ Cv,
                               int nnz) {
    __shared__ int sK[NNZMAX];
    __shared__ int cnt[DD];
    int tid = threadIdx.x;
    for (int t = tid; t < nnz; t += blockDim.x) sK[t] = Kv[t];
    for (int k = tid; k < DD; k += blockDim.x) cnt[k] = 0;
    __syncthreads();
    for (int t = tid; t < nnz; t += blockDim.x) atomicAdd(&cnt[sK[t]], 1);
    __syncthreads();
    // exclusive prefix over 248 buckets (single thread; ~250 adds, cheap)
    __shared__ int off[DD + 1];
    if (tid == 0) {
        int s = 0;
        for (int k = 0; k < DD; k++) { off[k] = s; s += cnt[k]; }
        off[DD] = s;
    }
    __syncthreads();
    if (blockIdx.x == 0)
        for (int k = tid; k <= DD; k += blockDim.x) g_rowptr[k] = off[k];
    int t = blockIdx.x * blockDim.x + tid;
    if (t < nnz) {
        int k = sK[t];
        int rank = 0;
        for (int t2 = 0; t2 < t; ++t2) rank += (sK[t2] == k);
        int pos = off[k] + rank;
        g_Is[pos] = Iv[t];
        g_Js[pos] = Jv[t];
        g_Cs[pos] = Cv[t];
    }
}

// S[tgt[e]] += proj[src[e]] : 64 threads per edge, float4 vectorized atomics
__global__ void scatter_edges_kernel(const int* __restrict__ ei,
                                     const float* __restrict__ proj,
                                     float* __restrict__ S, int E) {
    int gid = blockIdx.x * blockDim.x + threadIdx.x;
    int e = gid >> 6;
    int c = gid & 63;
    if (e >= E || c >= DD / 4) return;
    int s = ei[e];
    int t = ei[E + e];
    float4 v = *(const float4*)(proj + (size_t)s * DD + c * 4);
#if __CUDA_ARCH__ >= 900
    atomicAdd((float4*)(S + (size_t)t * DD + c * 4), v);
#else
    float* p = S + (size_t)t * DD + c * 4;
    atomicAdd(p + 0, v.x); atomicAdd(p + 1, v.y);
    atomicAdd(p + 2, v.z); atomicAdd(p + 3, v.w);
#endif
}

// agg[n,k] = sum_t C_t * S[n,I_t] * f[n,J_t]; emits bf16 split directly
__global__ void bracket_kernel(const float* __restrict__ S, const float* __restrict__ F,
                               __nv_bfloat16* __restrict__ Ahi,
                               __nv_bfloat16* __restrict__ Alo) {
    __shared__ float sS[DD];
    __shared__ float sF[DD];
    int n = blockIdx.x;
    int tid = threadIdx.x;
    if (tid < DD) {
        sS[tid] = S[n * DD + tid];
        sF[tid] = F[n * DD + tid];
    }
    __syncthreads();
    if (tid < DD) {
        int b = g_rowptr[tid];
        int e = g_rowptr[tid + 1];
        float acc = 0.f;
        for (int t = b; t < e; t++)
            acc += g_Cs[t] * sS[g_Is[t]] * sF[g_Js[t]];
        __nv_bfloat16 h = __float2bfloat16(acc);
        Ahi[n * DD + tid] = h;
        Alo[n * DD + tid] = __float2bfloat16(acc - __bfloat162float(h));
    }
}

// ---------------- warp-MMA (mma.sync bf16) split GEMM (proven config) --------
#define MMA16816(c, a, b)                                                     \
    asm volatile(                                                             \
        "mma.sync.aligned.m16n8k16.row.col.f32.bf16.bf16.f32 "                \
        "{%0,%1,%2,%3},{%4,%5,%6,%7},{%8,%9},{%0,%1,%2,%3};"                  \
        : "+f"((c)[0]), "+f"((c)[1]), "+f"((c)[2]), "+f"((c)[3])              \
        : "r"((a)[0]), "r"((a)[1]), "r"((a)[2]), "r"((a)[3]),                 \
          "r"((b)[0]), "r"((b)[1]))

#define LDSM4(r0, r1, r2, r3, addr)                                           \
    asm volatile("ldmatrix.sync.aligned.m8n8.x4.shared.b16 {%0,%1,%2,%3}, [%4];" \
                 : "=r"(r0), "=r"(r1), "=r"(r2), "=r"(r3) : "r"(addr))

#define CPASYNC16(saddr, gaddr, sz)                                           \
    asm volatile("cp.async.cg.shared.global [%0], [%1], 16, %2;"              \
                 :: "r"(saddr), "l"(gaddr), "r"(sz) : "memory")

#define BUF_BYTES   30720u
#define A_PLANE     10240u
#define B_OFF       20480u
#define B_PLANE     5120u
#define ROWB        80u
#define NSTAGE      3

__device__ __forceinline__ uint32_t smem_u32(const void* p) {
    uint32_t a;
    asm("{ .reg .u64 t; cvta.to.shared.u64 t, %1; cvt.u32.u64 %0, t; }"
        : "=r"(a) : "l"(p));
    return a;
}

template <int ACT, int SPLIT_OUT>
__global__ __launch_bounds__(256) void hmma_gemm(
    const __nv_bfloat16* __restrict__ Ah, const __nv_bfloat16* __restrict__ Al,
    const __nv_bfloat16* __restrict__ Bh, const __nv_bfloat16* __restrict__ Bl,
    const float* __restrict__ bias,
    float* __restrict__ Cf,
    __nv_bfloat16* __restrict__ Chi, __nv_bfloat16* __restrict__ Clo,
    int M, int N, int K)
{
    extern __shared__ char smem[];
    uint32_t sbase = smem_u32(smem);

    int tid = threadIdx.x;
    int wid = tid >> 5;
    int lane = tid & 31;
    int g = lane >> 2;
    int tg = lane & 3;
    int wm = wid >> 1;
    int wn = wid & 1;
    int m0 = blockIdx.x * 128;
    int n0 = blockIdx.y * 64;

    int lr = lane & 7;
    int lm01 = (lane >> 3) & 1;
    int lm23 = lane >> 4;

    float acc[2][4][4];
#pragma unroll
    for (int mi = 0; mi < 2; mi++)
#pragma unroll
        for (int ni = 0; ni < 4; ni++)
#pragma unroll
            for (int q = 0; q < 4; q++) acc[mi][ni][q] = 0.f;

    int nkc = (K + 31) >> 5;

    auto issue_chunk = [&](int c) {
        int kc = c << 5;
        uint32_t bufb = sbase + (uint32_t)(c % NSTAGE) * BUF_BYTES;
#pragma unroll
        for (int r = 0; r < 4; ++r) {
            int i = tid + (r << 8);
            int plane = i >> 9;
            int row = (i >> 2) & 127;
            int seg = i & 3;
            int gm = m0 + row;
            int k = kc + seg * 8;
            const __nv_bfloat16* src = (plane ? Al : Ah) + (size_t)gm * K + k;
            uint32_t dst = bufb + (uint32_t)plane * A_PLANE + (uint32_t)row * ROWB
                           + (uint32_t)seg * 16u;
            uint32_t sz = (gm < M && k < K) ? 16u : 0u;
            CPASYNC16(dst, src, sz);
        }
#pragma unroll
        for (int r = 0; r < 2; ++r) {
            int i = tid + (r << 8);
            int plane = i >> 8;
            int row = (i >> 2) & 63;
            int seg = i & 3;
            int gn = n0 + row;
            int k = kc + seg * 8;
            const __nv_bfloat16* src = (plane ? Bl : Bh) + (size_t)gn * K + k;
            uint32_t dst = bufb + B_OFF + (uint32_t)plane * B_PLANE
                           + (uint32_t)row * ROWB + (uint32_t)seg * 16u;
            uint32_t sz = (gn < N && k < K) ? 16u : 0u;
            CPASYNC16(dst, src, sz);
        }
        asm volatile("cp.async.commit_group;" ::: "memory");
    };

    issue_chunk(0);
    if (nkc > 1) issue_chunk(1);

    for (int c = 0; c < nkc; ++c) {
        if (c + 2 < nkc) {
            issue_chunk(c + 2);
            asm volatile("cp.async.wait_group 2;" ::: "memory");
        } else if (c + 1 < nkc) {
            asm volatile("cp.async.wait_group 1;" ::: "memory");
        } else {
            asm volatile("cp.async.wait_group 0;" ::: "memory");
        }
        __syncthreads();

        uint32_t abase = sbase + (uint32_t)(c % NSTAGE) * BUF_BYTES;
        uint32_t bbase = abase + B_OFF;
#pragma unroll
        for (int ks = 0; ks < 32; ks += 16) {
            uint32_t ah[2][4], al[2][4], bh[4][2], bl[4][2];
#pragma unroll
            for (int mi = 0; mi < 2; mi++) {
                uint32_t row = (uint32_t)(wm * 32 + mi * 16 + lm01 * 8 + lr);
                uint32_t col = (uint32_t)(ks + lm23 * 8);
                uint32_t off = row * ROWB + col * 2u;
                LDSM4(ah[mi][0], ah[mi][1], ah[mi][2], ah[mi][3], abase + off);
                LDSM4(al[mi][0], al[mi][1], al[mi][2], al[mi][3],
                      abase + A_PLANE + off);
            }
#pragma unroll
            for (int ng = 0; ng < 2; ng++) {
                uint32_t row = (uint32_t)(wn * 32 + ng * 16 + lm23 * 8 + lr);
                uint32_t col = (uint32_t)(ks + lm01 * 8);
                uint32_t off = row * ROWB + col * 2u;
                LDSM4(bh[2 * ng][0], bh[2 * ng][1], bh[2 * ng + 1][0],
                      bh[2 * ng + 1][1], bbase + off);
                LDSM4(bl[2 * ng][0], bl[2 * ng][1], bl[2 * ng + 1][0],
                      bl[2 * ng + 1][1], bbase + B_PLANE + off);
            }
#pragma unroll
            for (int mi = 0; mi < 2; mi++)
#pragma unroll
                for (int ni = 0; ni < 4; ni++) {
                    MMA16816(acc[mi][ni], ah[mi], bh[ni]);
                    MMA16816(acc[mi][ni], ah[mi], bl[ni]);
                    MMA16816(acc[mi][ni], al[mi], bh[ni]);
                }
        }
        __syncthreads();
    }

    // ---- epilogue ----
#pragma unroll
    for (int mi = 0; mi < 2; mi++) {
#pragma unroll
        for (int ni = 0; ni < 4; ni++) {
#pragma unroll
            for (int h = 0; h < 2; h++) {
                int gm = m0 + wm * 32 + mi * 16 + g + h * 8;
                if (gm >= M) continue;
#pragma unroll
                for (int q = 0; q < 2; q++) {
                    int gn = n0 + wn * 32 + ni * 8 + tg * 2 + q;
                    if (gn >= N) continue;
                    float v = acc[mi][ni][h * 2 + q];
                    if (bias) v += bias[gn];
                    if (ACT == 1) v = v / (1.f + expf(-v));
                    if (SPLIT_OUT == 1) {
                        __nv_bfloat16 hh = __float2bfloat16(v);
                        Chi[(size_t)gm * N + gn] = hh;
                        Clo[(size_t)gm * N + gn] =
                            __float2bfloat16(v - __bfloat162float(hh));
                    } else {
                        Cf[(size_t)gm * N + gn] = v;
                    }
                }
            }
        }
    }
}

// ---------------- residual + LayerNorm (shuffle reductions) ----------------
__global__ void ln_kernel(const float* __restrict__ F, const float* __restrict__ h2,
                          const float* __restrict__ gamma, const float* __restrict__ beta,
                          float* __restrict__ out) {
    __shared__ float wred[8];
    int n = blockIdx.x;
    int tid = threadIdx.x;
    int lane = tid & 31;
    int wid = tid >> 5;
    float x = (tid < DD) ? (F[n * DD + tid] + h2[n * DD + tid]) : 0.f;

    float s = x;
#pragma unroll
    for (int o = 16; o > 0; o >>= 1) s += __shfl_xor_sync(0xFFFFFFFFu, s, o);
    if (lane == 0) wred[wid] = s;
    __syncthreads();
    float mu = 0.f;
#pragma unroll
    for (int i = 0; i < 8; i++) mu += wred[i];
    mu *= (1.f / DD);
    __syncthreads();

    float xc = (tid < DD) ? (x - mu) : 0.f;
    float s2 = xc * xc;
#pragma unroll
    for (int o = 16; o > 0; o >>= 1) s2 += __shfl_xor_sync(0xFFFFFFFFu, s2, o);
    if (lane == 0) wred[wid] = s2;
    __syncthreads();
    float var = 0.f;
#pragma unroll
    for (int i = 0; i < 8; i++) var += wred[i];
    var *= (1.f / DD);
    float r = rsqrtf(var + 1e-5f);
    if (tid < DD)
        out[n * DD + tid] = xc * r * gamma[tid] + beta[tid];
}

// ---------------- launcher ----------------
extern "C" void kernel_launch(void* const* d_in, const int* in_sizes, int n_in,
                              void* d_out, int out_size) {
    const float* features = (const float*)d_in[0];
    const int*   ei       = (const int*)d_in[1];
    const float* Wmsg     = (const float*)d_in[2];
    const float* W1       = (const float*)d_in[3];
    const float* b1       = (const float*)d_in[4];
    const float* W2       = (const float*)d_in[5];
    const float* b2       = (const float*)d_in[6];
    const float* gamma    = (const float*)d_in[7];
    const float* beta     = (const float*)d_in[8];
    const int*   Iv       = (const int*)d_in[9];
    const int*   Jv       = (const int*)d_in[10];
    const int*   Kv       = (const int*)d_in[11];
    const float* Cv       = (const float*)d_in[12];
    float* out = (float*)d_out;

    int N   = in_sizes[0] / DD;
    int E   = in_sizes[1] / 2;
    int nnz = in_sizes[9];

    float *p_proj, *p_S, *p_h2;
    __nv_bfloat16 *p_fhi, *p_flo, *p_agghi, *p_agglo, *p_hidhi, *p_hidlo;
    __nv_bfloat16 *p_wmhi, *p_wmlo, *p_w1hi, *p_w1lo, *p_w2hi, *p_w2lo;
    cudaGetSymbolAddress((void**)&p_proj,  g_proj);
    cudaGetSymbolAddress((void**)&p_S,     g_S);
    cudaGetSymbolAddress((void**)&p_h2,    g_h2);
    cudaGetSymbolAddress((void**)&p_fhi,   g_fhi);
    cudaGetSymbolAddress((void**)&p_flo,   g_flo);
    cudaGetSymbolAddress((void**)&p_agghi, g_agghi);
    cudaGetSymbolAddress((void**)&p_agglo, g_agglo);
    cudaGetSymbolAddress((void**)&p_hidhi, g_hidhi);
    cudaGetSymbolAddress((void**)&p_hidlo, g_hidlo);
    cudaGetSymbolAddress((void**)&p_wmhi,  g_wmhi);
    cudaGetSymbolAddress((void**)&p_wmlo,  g_wmlo);
    cudaGetSymbolAddress((void**)&p_w1hi,  g_w1hi);
    cudaGetSymbolAddress((void**)&p_w1lo,  g_w1lo);
    cudaGetSymbolAddress((void**)&p_w2hi,  g_w2hi);
    cudaGetSymbolAddress((void**)&p_w2lo,  g_w2lo);

    const int SMEM_SZ = NSTAGE * 30720;
    cudaFuncSetAttribute(hmma_gemm<0, 0>, cudaFuncAttributeMaxDynamicSharedMemorySize, SMEM_SZ);
    cudaFuncSetAttribute(hmma_gemm<1, 1>, cudaFuncAttributeMaxDynamicSharedMemorySize, SMEM_SZ);

    // #1: features split + zero S
    prep_feat_kernel<<<512, 256>>>(features, p_fhi, p_flo, p_S, N * DD);
    // #2: weight splits
    prep_w_kernel<<<256, 256>>>(Wmsg, W1, W2, p_wmhi, p_wmlo,
                                p_w1hi, p_w1lo, p_w2hi, p_w2lo);
    // #3: deterministic parallel CSR
    build_csr_fast<<<(nnz + 255) / 256, 256>>>(Iv, Jv, Kv, Cv, nnz);

    int mtiles = (N + 127) / 128;

    // #4 (profiled): proj = features @ Wmsg^T
    hmma_gemm<0, 0><<<dim3(mtiles, (DD + 63) / 64), 256, SMEM_SZ>>>(
        p_fhi, p_flo, p_wmhi, p_wmlo, nullptr, p_proj, nullptr, nullptr, N, DD, DD);

    // #5: S[tgt] += proj[src]
    scatter_edges_kernel<<<(E * 64 + 255) / 256, 256>>>(ei, p_proj, p_S, E);

    // #6: agg = bracket(S, features), pre-split
    bracket_kernel<<<N, 256>>>(p_S, features, p_agghi, p_agglo);

    // #7: hidden = silu(agg @ W1^T + b1), pre-split
    hmma_gemm<1, 1><<<dim3(mtiles, (HH + 63) / 64), 256, SMEM_SZ>>>(
        p_agghi, p_agglo, p_w1hi, p_w1lo, b1, nullptr, p_hidhi, p_hidlo, N, HH, DD);

    // #8: h2 = hidden @ W2^T + b2
    hmma_gemm<0, 0><<<dim3(mtiles, (DD + 63) / 64), 256, SMEM_SZ>>>(
        p_hidhi, p_hidlo, p_w2hi, p_w2lo, b2, p_h2, nullptr, nullptr, N, DD, HH);

    // #9: out = LayerNorm(features + h2)
    ln_kernel<<<N, 256>>>(features, p_h2, gamma, beta, out);
}

// round 9
// speedup vs baseline: 1.6897x; 1.0470x over previous
#include <cuda_runtime.h>
#include <cuda_bf16.h>
#include <math.h>
#include <stdint.h>

#define DD   248
#define HH   512
#define NMAX 10000
#define NNZMAX 4096

// ---------------- scratch (device globals; no allocs allowed) ----------------
__device__ float g_proj[NMAX * DD];
__device__ float g_S[NMAX * DD];
__device__ float g_h2[NMAX * DD];
__device__ __align__(16) __nv_bfloat16 g_fhi[NMAX * DD];
__device__ __align__(16) __nv_bfloat16 g_flo[NMAX * DD];
__device__ __align__(16) __nv_bfloat16 g_agghi[NMAX * DD];
__device__ __align__(16) __nv_bfloat16 g_agglo[NMAX * DD];
__device__ __align__(16) __nv_bfloat16 g_hidhi[NMAX * HH];
__device__ __align__(16) __nv_bfloat16 g_hidlo[NMAX * HH];
__device__ __align__(16) __nv_bfloat16 g_wmhi[DD * DD];
__device__ __align__(16) __nv_bfloat16 g_wmlo[DD * DD];
__device__ __align__(16) __nv_bfloat16 g_w1hi[HH * DD];
__device__ __align__(16) __nv_bfloat16 g_w1lo[HH * DD];
__device__ __align__(16) __nv_bfloat16 g_w2hi[DD * HH];
__device__ __align__(16) __nv_bfloat16 g_w2lo[DD * HH];
__device__ int   g_rowptr[DD + 1];
__device__ int   g_Is[NNZMAX];
__device__ int   g_Js[NNZMAX];
__device__ float g_Cs[NNZMAX];

// ---------------- splits ----------------
__device__ __forceinline__ void split1(const float* __restrict__ x,
                                       __nv_bfloat16* __restrict__ hi,
                                       __nv_bfloat16* __restrict__ lo, int i) {
    float v = x[i];
    __nv_bfloat16 h = __float2bfloat16(v);
    hi[i] = h;
    lo[i] = __float2bfloat16(v - __bfloat162float(h));
}

// launch #1: features split + zero S
__global__ void prep_feat_kernel(const float* __restrict__ F,
                                 __nv_bfloat16* __restrict__ fhi,
                                 __nv_bfloat16* __restrict__ flo,
                                 float* __restrict__ S, int nfeat) {
    int i = blockIdx.x * blockDim.x + threadIdx.x;
    int stride = gridDim.x * blockDim.x;
    for (; i < nfeat; i += stride) {
        split1(F, fhi, flo, i);
        S[i] = 0.f;
    }
}

// launch #2: all weight splits
__global__ void prep_w_kernel(const float* __restrict__ Wmsg,
                              const float* __restrict__ W1,
                              const float* __restrict__ W2,
                              __nv_bfloat16* __restrict__ wmhi, __nv_bfloat16* __restrict__ wmlo,
                              __nv_bfloat16* __restrict__ w1hi, __nv_bfloat16* __restrict__ w1lo,
                              __nv_bfloat16* __restrict__ w2hi, __nv_bfloat16* __restrict__ w2lo) {
    const int s1 = DD * DD;
    const int s2 = HH * DD;
    const int s3 = DD * HH;
    int total = s1 + s2 + s3;
    int i = blockIdx.x * blockDim.x + threadIdx.x;
    int stride = gridDim.x * blockDim.x;
    for (; i < total; i += stride) {
        if (i < s1)            split1(Wmsg, wmhi, wmlo, i);
        else if (i < s1 + s2)  split1(W1, w1hi, w1lo, i - s1);
        else                   split1(W2, w2hi, w2lo, i - s1 - s2);
    }
}

// launch #3: deterministic parallel CSR build (stable rank-by-scan).
__global__ void build_csr_fast(const int* __restrict__ Iv, const int* __restrict__ Jv,
                               const int* __restrict__ Kv, const float* __restrict__ Cv,
                               int nnz) {
    __shared__ int sK[NNZMAX];
    __shared__ int cnt[DD];
    int tid = threadIdx.x;
    for (int t = tid; t < nnz; t += blockDim.x) sK[t] = Kv[t];
    for (int k = tid; k < DD; k += blockDim.x) cnt[k] = 0;
    __syncthreads();
    for (int t = tid; t < nnz; t += blockDim.x) atomicAdd(&cnt[sK[t]], 1);
    __syncthreads();
    __shared__ int off[DD + 1];
    if (tid == 0) {
        int s = 0;
        for (int k = 0; k < DD; k++) { off[k] = s; s += cnt[k]; }
        off[DD] = s;
    }
    __syncthreads();
    if (blockIdx.x == 0)
        for (int k = tid; k <= DD; k += blockDim.x) g_rowptr[k] = off[k];
    int t = blockIdx.x * blockDim.x + tid;
    if (t < nnz) {
        int k = sK[t];
        int rank = 0;
        for (int t2 = 0; t2 < t; ++t2) rank += (sK[t2] == k);
        int pos = off[k] + rank;
        g_Is[pos] = Iv[t];
        g_Js[pos] = Jv[t];
        g_Cs[pos] = Cv[t];
    }
}

// S[tgt[e]] += proj[src[e]] : 64 threads per edge, float4 vectorized atomics
__global__ void scatter_edges_kernel(const int* __restrict__ ei,
                                     const float* __restrict__ proj,
                                     float* __restrict__ S, int E) {
    int gid = blockIdx.x * blockDim.x + threadIdx.x;
    int e = gid >> 6;
    int c = gid & 63;
    if (e >= E || c >= DD / 4) return;
    int s = ei[e];
    int t = ei[E + e];
    float4 v = *(const float4*)(proj + (size_t)s * DD + c * 4);
#if __CUDA_ARCH__ >= 900
    atomicAdd((float4*)(S + (size_t)t * DD + c * 4), v);
#else
    float* p = S + (size_t)t * DD + c * 4;
    atomicAdd(p + 0, v.x); atomicAdd(p + 1, v.y);
    atomicAdd(p + 2, v.z); atomicAdd(p + 3, v.w);
#endif
}

// agg[n,k] = sum_t C_t * S[n,I_t] * f[n,J_t]; emits bf16 split directly
__global__ void bracket_kernel(const float* __restrict__ S, const float* __restrict__ F,
                               __nv_bfloat16* __restrict__ Ahi,
                               __nv_bfloat16* __restrict__ Alo) {
    __shared__ float sS[DD];
    __shared__ float sF[DD];
    int n = blockIdx.x;
    int tid = threadIdx.x;
    if (tid < DD) {
        sS[tid] = S[n * DD + tid];
        sF[tid] = F[n * DD + tid];
    }
    __syncthreads();
    if (tid < DD) {
        int b = g_rowptr[tid];
        int e = g_rowptr[tid + 1];
        float acc = 0.f;
        for (int t = b; t < e; t++)
            acc += g_Cs[t] * sS[g_Is[t]] * sF[g_Js[t]];
        __nv_bfloat16 h = __float2bfloat16(acc);
        Ahi[n * DD + tid] = h;
        Alo[n * DD + tid] = __float2bfloat16(acc - __bfloat162float(h));
    }
}

// ---------------- warp-MMA (mma.sync bf16) split GEMM --------
// CTA 128x64, 8 warps 4x2, warp tile 32x32, BK=32, 2-stage cp.async,
// ldmatrix frags, PRODUCT-MAJOR MMA order (acc reuse distance 8).
#define MMA16816(c, a, b)                                                     \
    asm volatile(                                                             \
        "mma.sync.aligned.m16n8k16.row.col.f32.bf16.bf16.f32 "                \
        "{%0,%1,%2,%3},{%4,%5,%6,%7},{%8,%9},{%0,%1,%2,%3};"                  \
        : "+f"((c)[0]), "+f"((c)[1]), "+f"((c)[2]), "+f"((c)[3])              \
        : "r"((a)[0]), "r"((a)[1]), "r"((a)[2]), "r"((a)[3]),                 \
          "r"((b)[0]), "r"((b)[1]))

#define LDSM4(r0, r1, r2, r3, addr)                                           \
    asm volatile("ldmatrix.sync.aligned.m8n8.x4.shared.b16 {%0,%1,%2,%3}, [%4];" \
                 : "=r"(r0), "=r"(r1), "=r"(r2), "=r"(r3) : "r"(addr))

#define CPASYNC16(saddr, gaddr, sz)                                           \
    asm volatile("cp.async.cg.shared.global [%0], [%1], 16, %2;"              \
                 :: "r"(saddr), "l"(gaddr), "r"(sz) : "memory")

#define BUF_BYTES   30720u
#define A_PLANE     10240u
#define B_OFF       20480u
#define B_PLANE     5120u
#define ROWB        80u
#define NSTAGE      2

__device__ __forceinline__ uint32_t smem_u32(const void* p) {
    uint32_t a;
    asm("{ .reg .u64 t; cvta.to.shared.u64 t, %1; cvt.u32.u64 %0, t; }"
        : "=r"(a) : "l"(p));
    return a;
}

template <int ACT, int SPLIT_OUT>
__global__ __launch_bounds__(256) void hmma_gemm(
    const __nv_bfloat16* __restrict__ Ah, const __nv_bfloat16* __restrict__ Al,
    const __nv_bfloat16* __restrict__ Bh, const __nv_bfloat16* __restrict__ Bl,
    const float* __restrict__ bias,
    float* __restrict__ Cf,
    __nv_bfloat16* __restrict__ Chi, __nv_bfloat16* __restrict__ Clo,
    int M, int N, int K)
{
    extern __shared__ char smem[];
    uint32_t sbase = smem_u32(smem);

    int tid = threadIdx.x;
    int wid = tid >> 5;
    int lane = tid & 31;
    int g = lane >> 2;
    int tg = lane & 3;
    int wm = wid >> 1;
    int wn = wid & 1;
    int m0 = blockIdx.x * 128;
    int n0 = blockIdx.y * 64;

    int lr = lane & 7;
    int lm01 = (lane >> 3) & 1;
    int lm23 = lane >> 4;

    float acc[2][4][4];
#pragma unroll
    for (int mi = 0; mi < 2; mi++)
#pragma unroll
        for (int ni = 0; ni < 4; ni++)
#pragma unroll
            for (int q = 0; q < 4; q++) acc[mi][ni][q] = 0.f;

    int nkc = (K + 31) >> 5;

    auto issue_chunk = [&](int c) {
        int kc = c << 5;
        uint32_t bufb = sbase + (uint32_t)(c & 1) * BUF_BYTES;
#pragma unroll
        for (int r = 0; r < 4; ++r) {
            int i = tid + (r << 8);
            int plane = i >> 9;
            int row = (i >> 2) & 127;
            int seg = i & 3;
            int gm = m0 + row;
            int k = kc + seg * 8;
            const __nv_bfloat16* src = (plane ? Al : Ah) + (size_t)gm * K + k;
            uint32_t dst = bufb + (uint32_t)plane * A_PLANE + (uint32_t)row * ROWB
                           + (uint32_t)seg * 16u;
            uint32_t sz = (gm < M && k < K) ? 16u : 0u;
            CPASYNC16(dst, src, sz);
        }
#pragma unroll
        for (int r = 0; r < 2; ++r) {
            int i = tid + (r << 8);
            int plane = i >> 8;
            int row = (i >> 2) & 63;
            int seg = i & 3;
            int gn = n0 + row;
            int k = kc + seg * 8;
            const __nv_bfloat16* src = (plane ? Bl : Bh) + (size_t)gn * K + k;
            uint32_t dst = bufb + B_OFF + (uint32_t)plane * B_PLANE
                           + (uint32_t)row * ROWB + (uint32_t)seg * 16u;
            uint32_t sz = (gn < N && k < K) ? 16u : 0u;
            CPASYNC16(dst, src, sz);
        }
        asm volatile("cp.async.commit_group;" ::: "memory");
    };

    issue_chunk(0);

    for (int c = 0; c < nkc; ++c) {
        if (c + 1 < nkc) {
            issue_chunk(c + 1);
            asm volatile("cp.async.wait_group 1;" ::: "memory");
        } else {
            asm volatile("cp.async.wait_group 0;" ::: "memory");
        }
        __syncthreads();

        uint32_t abase = sbase + (uint32_t)(c & 1) * BUF_BYTES;
        uint32_t bbase = abase + B_OFF;
#pragma unroll
        for (int ks = 0; ks < 32; ks += 16) {
            uint32_t ah[2][4], al[2][4], bh[4][2], bl[4][2];
#pragma unroll
            for (int mi = 0; mi < 2; mi++) {
                uint32_t row = (uint32_t)(wm * 32 + mi * 16 + lm01 * 8 + lr);
                uint32_t col = (uint32_t)(ks + lm23 * 8);
                uint32_t off = row * ROWB + col * 2u;
                LDSM4(ah[mi][0], ah[mi][1], ah[mi][2], ah[mi][3], abase + off);
                LDSM4(al[mi][0], al[mi][1], al[mi][2], al[mi][3],
                      abase + A_PLANE + off);
            }
#pragma unroll
            for (int ng = 0; ng < 2; ng++) {
                uint32_t row = (uint32_t)(wn * 32 + ng * 16 + lm23 * 8 + lr);
                uint32_t col = (uint32_t)(ks + lm01 * 8);
                uint32_t off = row * ROWB + col * 2u;
                LDSM4(bh[2 * ng][0], bh[2 * ng][1], bh[2 * ng + 1][0],
                      bh[2 * ng + 1][1], bbase + off);
                LDSM4(bl[2 * ng][0], bl[2 * ng][1], bl[2 * ng + 1][0],
                      bl[2 * ng + 1][1], bbase + B_PLANE + off);
            }
            // product-major: 8 independent MMAs per pass, acc reuse distance 8
#pragma unroll
            for (int mi = 0; mi < 2; mi++)
#pragma unroll
                for (int ni = 0; ni < 4; ni++)
                    MMA16816(acc[mi][ni], ah[mi], bh[ni]);
#pragma unroll
            for (int mi = 0; mi < 2; mi++)
#pragma unroll
                for (int ni = 0; ni < 4; ni++)
                    MMA16816(acc[mi][ni], ah[mi], bl[ni]);
#pragma unroll
            for (int mi = 0; mi < 2; mi++)
#pragma unroll
                for (int ni = 0; ni < 4; ni++)
                    MMA16816(acc[mi][ni], al[mi], bh[ni]);
        }
        __syncthreads();
    }

    // ---- epilogue ----
#pragma unroll
    for (int mi = 0; mi < 2; mi++) {
#pragma unroll
        for (int ni = 0; ni < 4; ni++) {
#pragma unroll
            for (int h = 0; h < 2; h++) {
                int gm = m0 + wm * 32 + mi * 16 + g + h * 8;
                if (gm >= M) continue;
#pragma unroll
                for (int q = 0; q < 2; q++) {
                    int gn = n0 + wn * 32 + ni * 8 + tg * 2 + q;
                    if (gn >= N) continue;
                    float v = acc[mi][ni][h * 2 + q];
                    if (bias) v += bias[gn];
                    if (ACT == 1) v = v / (1.f + expf(-v));
                    if (SPLIT_OUT == 1) {
                        __nv_bfloat16 hh = __float2bfloat16(v);
                        Chi[(size_t)gm * N + gn] = hh;
                        Clo[(size_t)gm * N + gn] =
                            __float2bfloat16(v - __bfloat162float(hh));
                    } else {
                        Cf[(size_t)gm * N + gn] = v;
                    }
                }
            }
        }
    }
}

// ---------------- residual + LayerNorm (shuffle reductions) ----------------
__global__ void ln_kernel(const float* __restrict__ F, const float* __restrict__ h2,
                          const float* __restrict__ gamma, const float* __restrict__ beta,
                          float* __restrict__ out) {
    __shared__ float wred[8];
    int n = blockIdx.x;
    int tid = threadIdx.x;
    int lane = tid & 31;
    int wid = tid >> 5;
    float x = (tid < DD) ? (F[n * DD + tid] + h2[n * DD + tid]) : 0.f;

    float s = x;
#pragma unroll
    for (int o = 16; o > 0; o >>= 1) s += __shfl_xor_sync(0xFFFFFFFFu, s, o);
    if (lane == 0) wred[wid] = s;
    __syncthreads();
    float mu = 0.f;
#pragma unroll
    for (int i = 0; i < 8; i++) mu += wred[i];
    mu *= (1.f / DD);
    __syncthreads();

    float xc = (tid < DD) ? (x - mu) : 0.f;
    float s2 = xc * xc;
#pragma unroll
    for (int o = 16; o > 0; o >>= 1) s2 += __shfl_xor_sync(0xFFFFFFFFu, s2, o);
    if (lane == 0) wred[wid] = s2;
    __syncthreads();
    float var = 0.f;
#pragma unroll
    for (int i = 0; i < 8; i++) var += wred[i];
    var *= (1.f / DD);
    float r = rsqrtf(var + 1e-5f);
    if (tid < DD)
        out[n * DD + tid] = xc * r * gamma[tid] + beta[tid];
}

// ---------------- launcher ----------------
extern "C" void kernel_launch(void* const* d_in, const int* in_sizes, int n_in,
                              void* d_out, int out_size) {
    const float* features = (const float*)d_in[0];
    const int*   ei       = (const int*)d_in[1];
    const float* Wmsg     = (const float*)d_in[2];
    const float* W1       = (const float*)d_in[3];
    const float* b1       = (const float*)d_in[4];
    const float* W2       = (const float*)d_in[5];
    const float* b2       = (const float*)d_in[6];
    const float* gamma    = (const float*)d_in[7];
    const float* beta     = (const float*)d_in[8];
    const int*   Iv       = (const int*)d_in[9];
    const int*   Jv       = (const int*)d_in[10];
    const int*   Kv       = (const int*)d_in[11];
    const float* Cv       = (const float*)d_in[12];
    float* out = (float*)d_out;

    int N   = in_sizes[0] / DD;
    int E   = in_sizes[1] / 2;
    int nnz = in_sizes[9];

    float *p_proj, *p_S, *p_h2;
    __nv_bfloat16 *p_fhi, *p_flo, *p_agghi, *p_agglo, *p_hidhi, *p_hidlo;
    __nv_bfloat16 *p_wmhi, *p_wmlo, *p_w1hi, *p_w1lo, *p_w2hi, *p_w2lo;
    cudaGetSymbolAddress((void**)&p_proj,  g_proj);
    cudaGetSymbolAddress((void**)&p_S,     g_S);
    cudaGetSymbolAddress((void**)&p_h2,    g_h2);
    cudaGetSymbolAddress((void**)&p_fhi,   g_fhi);
    cudaGetSymbolAddress((void**)&p_flo,   g_flo);
    cudaGetSymbolAddress((void**)&p_agghi, g_agghi);
    cudaGetSymbolAddress((void**)&p_agglo, g_agglo);
    cudaGetSymbolAddress((void**)&p_hidhi, g_hidhi);
    cudaGetSymbolAddress((void**)&p_hidlo, g_hidlo);
    cudaGetSymbolAddress((void**)&p_wmhi,  g_wmhi);
    cudaGetSymbolAddress((void**)&p_wmlo,  g_wmlo);
    cudaGetSymbolAddress((void**)&p_w1hi,  g_w1hi);
    cudaGetSymbolAddress((void**)&p_w1lo,  g_w1lo);
    cudaGetSymbolAddress((void**)&p_w2hi,  g_w2hi);
    cudaGetSymbolAddress((void**)&p_w2lo,  g_w2lo);

    const int SMEM_SZ = NSTAGE * 30720;
    cudaFuncSetAttribute(hmma_gemm<0, 0>, cudaFuncAttributeMaxDynamicSharedMemorySize, SMEM_SZ);
    cudaFuncSetAttribute(hmma_gemm<1, 1>, cudaFuncAttributeMaxDynamicSharedMemorySize, SMEM_SZ);

    // #1: features split + zero S
    prep_feat_kernel<<<512, 256>>>(features, p_fhi, p_flo, p_S, N * DD);
    // #2: weight splits
    prep_w_kernel<<<256, 256>>>(Wmsg, W1, W2, p_wmhi, p_wmlo,
                                p_w1hi, p_w1lo, p_w2hi, p_w2lo);
    // #3: deterministic parallel CSR
    build_csr_fast<<<(nnz + 255) / 256, 256>>>(Iv, Jv, Kv, Cv, nnz);

    int mtiles = (N + 127) / 128;

    // #4 (profiled): proj = features @ Wmsg^T
    hmma_gemm<0, 0><<<dim3(mtiles, (DD + 63) / 64), 256, SMEM_SZ>>>(
        p_fhi, p_flo, p_wmhi, p_wmlo, nullptr, p_proj, nullptr, nullptr, N, DD, DD);

    // #5: S[tgt] += proj[src]
    scatter_edges_kernel<<<(E * 64 + 255) / 256, 256>>>(ei, p_proj, p_S, E);

    // #6: agg = bracket(S, features), pre-split
    bracket_kernel<<<N, 256>>>(p_S, features, p_agghi, p_agglo);

    // #7: hidden = silu(agg @ W1^T + b1), pre-split
    hmma_gemm<1, 1><<<dim3(mtiles, (HH + 63) / 64), 256, SMEM_SZ>>>(
        p_agghi, p_agglo, p_w1hi, p_w1lo, b1, nullptr, p_hidhi, p_hidlo, N, HH, DD);

    // #8: h2 = hidden @ W2^T + b2
    hmma_gemm<0, 0><<<dim3(mtiles, (DD + 63) / 64), 256, SMEM_SZ>>>(
        p_hidhi, p_hidlo, p_w2hi, p_w2lo, b2, p_h2, nullptr, nullptr, N, DD, HH);

    // #9: out = LayerNorm(features + h2)
    ln_kernel<<<N, 256>>>(features, p_h2, gamma, beta, out);
}

// round 10
// speedup vs baseline: 1.7021x; 1.0074x over previous
#include <cuda_runtime.h>
#include <cuda_bf16.h>
#include <math.h>
#include <stdint.h>

#define DD   248
#define HH   512
#define NMAX 10000
#define NNZMAX 4096

// ---------------- scratch (device globals; no allocs allowed) ----------------
__device__ float g_proj[NMAX * DD];
__device__ float g_S[NMAX * DD];
__device__ float g_h2[NMAX * DD];
__device__ __align__(16) __nv_bfloat16 g_fhi[NMAX * DD];
__device__ __align__(16) __nv_bfloat16 g_flo[NMAX * DD];
__device__ __align__(16) __nv_bfloat16 g_agghi[NMAX * DD];
__device__ __align__(16) __nv_bfloat16 g_agglo[NMAX * DD];
__device__ __align__(16) __nv_bfloat16 g_hidhi[NMAX * HH];
__device__ __align__(16) __nv_bfloat16 g_hidlo[NMAX * HH];
__device__ __align__(16) __nv_bfloat16 g_wmhi[DD * DD];
__device__ __align__(16) __nv_bfloat16 g_wmlo[DD * DD];
__device__ __align__(16) __nv_bfloat16 g_w1hi[HH * DD];
__device__ __align__(16) __nv_bfloat16 g_w1lo[HH * DD];
__device__ __align__(16) __nv_bfloat16 g_w2hi[DD * HH];
__device__ __align__(16) __nv_bfloat16 g_w2lo[DD * HH];
__device__ int   g_rowptr[DD + 1];
__device__ int   g_Is[NNZMAX];
__device__ int   g_Js[NNZMAX];
__device__ float g_Cs[NNZMAX];

// ---------------- splits ----------------
__device__ __forceinline__ void split1(const float* __restrict__ x,
                                       __nv_bfloat16* __restrict__ hi,
                                       __nv_bfloat16* __restrict__ lo, int i) {
    float v = x[i];
    __nv_bfloat16 h = __float2bfloat16(v);
    hi[i] = h;
    lo[i] = __float2bfloat16(v - __bfloat162float(h));
}

// launch #1: features split + zero S
__global__ void prep_feat_kernel(const float* __restrict__ F,
                                 __nv_bfloat16* __restrict__ fhi,
                                 __nv_bfloat16* __restrict__ flo,
                                 float* __restrict__ S, int nfeat) {
    int i = blockIdx.x * blockDim.x + threadIdx.x;
    int stride = gridDim.x * blockDim.x;
    for (; i < nfeat; i += stride) {
        split1(F, fhi, flo, i);
        S[i] = 0.f;
    }
}

// launch #2: all weight splits
__global__ void prep_w_kernel(const float* __restrict__ Wmsg,
                              const float* __restrict__ W1,
                              const float* __restrict__ W2,
                              __nv_bfloat16* __restrict__ wmhi, __nv_bfloat16* __restrict__ wmlo,
                              __nv_bfloat16* __restrict__ w1hi, __nv_bfloat16* __restrict__ w1lo,
                              __nv_bfloat16* __restrict__ w2hi, __nv_bfloat16* __restrict__ w2lo) {
    const int s1 = DD * DD;
    const int s2 = HH * DD;
    const int s3 = DD * HH;
    int total = s1 + s2 + s3;
    int i = blockIdx.x * blockDim.x + threadIdx.x;
    int stride = gridDim.x * blockDim.x;
    for (; i < total; i += stride) {
        if (i < s1)            split1(Wmsg, wmhi, wmlo, i);
        else if (i < s1 + s2)  split1(W1, w1hi, w1lo, i - s1);
        else                   split1(W2, w2hi, w2lo, i - s1 - s2);
    }
}

// launch #3: deterministic parallel CSR build (stable rank-by-scan).
__global__ void build_csr_fast(const int* __restrict__ Iv, const int* __restrict__ Jv,
                               const int* __restrict__ Kv, const float* __restrict__ Cv,
                               int nnz) {
    __shared__ int sK[NNZMAX];
    __shared__ int cnt[DD];
    int tid = threadIdx.x;
    for (int t = tid; t < nnz; t += blockDim.x) sK[t] = Kv[t];
    for (int k = tid; k < DD; k += blockDim.x) cnt[k] = 0;
    __syncthreads();
    for (int t = tid; t < nnz; t += blockDim.x) atomicAdd(&cnt[sK[t]], 1);
    __syncthreads();
    __shared__ int off[DD + 1];
    if (tid == 0) {
        int s = 0;
        for (int k = 0; k < DD; k++) { off[k] = s; s += cnt[k]; }
        off[DD] = s;
    }
    __syncthreads();
    if (blockIdx.x == 0)
        for (int k = tid; k <= DD; k += blockDim.x) g_rowptr[k] = off[k];
    int t = blockIdx.x * blockDim.x + tid;
    if (t < nnz) {
        int k = sK[t];
        int rank = 0;
        for (int t2 = 0; t2 < t; ++t2) rank += (sK[t2] == k);
        int pos = off[k] + rank;
        g_Is[pos] = Iv[t];
        g_Js[pos] = Jv[t];
        g_Cs[pos] = Cv[t];
    }
}

// S[tgt[e]] += proj[src[e]] : 64 threads per edge, float4 vectorized atomics
__global__ void scatter_edges_kernel(const int* __restrict__ ei,
                                     const float* __restrict__ proj,
                                     float* __restrict__ S, int E) {
    int gid = blockIdx.x * blockDim.x + threadIdx.x;
    int e = gid >> 6;
    int c = gid & 63;
    if (e >= E || c >= DD / 4) return;
    int s = ei[e];
    int t = ei[E + e];
    float4 v = *(const float4*)(proj + (size_t)s * DD + c * 4);
#if __CUDA_ARCH__ >= 900
    atomicAdd((float4*)(S + (size_t)t * DD + c * 4), v);
#else
    float* p = S + (size_t)t * DD + c * 4;
    atomicAdd(p + 0, v.x); atomicAdd(p + 1, v.y);
    atomicAdd(p + 2, v.z); atomicAdd(p + 3, v.w);
#endif
}

// agg[n,k] = sum_t C_t * S[n,I_t] * f[n,J_t]; emits bf16 split directly
__global__ void bracket_kernel(const float* __restrict__ S, const float* __restrict__ F,
                               __nv_bfloat16* __restrict__ Ahi,
                               __nv_bfloat16* __restrict__ Alo) {
    __shared__ float sS[DD];
    __shared__ float sF[DD];
    int n = blockIdx.x;
    int tid = threadIdx.x;
    if (tid < DD) {
        sS[tid] = S[n * DD + tid];
        sF[tid] = F[n * DD + tid];
    }
    __syncthreads();
    if (tid < DD) {
        int b = g_rowptr[tid];
        int e = g_rowptr[tid + 1];
        float acc = 0.f;
        for (int t = b; t < e; t++)
            acc += g_Cs[t] * sS[g_Is[t]] * sF[g_Js[t]];
        __nv_bfloat16 h = __float2bfloat16(acc);
        Ahi[n * DD + tid] = h;
        Alo[n * DD + tid] = __float2bfloat16(acc - __bfloat162float(h));
    }
}

// ---------------- warp-MMA (mma.sync bf16) split GEMM, BK=64 --------
// C[M,N] = A[M,K] @ B[N,K]^T via AhBh + AhBl + AlBh  (fp32 accumulate)
// CTA 128x64, 8 warps 4x2, warp tile 32x32, BK=64 (4 k16 steps/chunk),
// 2-stage cp.async, ldmatrix frags, product-major MMA order.
// Rows padded to 144B (conflict-free: 4r mod 32 distinct; 16B aligned).
#define MMA16816(c, a, b)                                                     \
    asm volatile(                                                             \
        "mma.sync.aligned.m16n8k16.row.col.f32.bf16.bf16.f32 "                \
        "{%0,%1,%2,%3},{%4,%5,%6,%7},{%8,%9},{%0,%1,%2,%3};"                  \
        : "+f"((c)[0]), "+f"((c)[1]), "+f"((c)[2]), "+f"((c)[3])              \
        : "r"((a)[0]), "r"((a)[1]), "r"((a)[2]), "r"((a)[3]),                 \
          "r"((b)[0]), "r"((b)[1]))

#define LDSM4(r0, r1, r2, r3, addr)                                           \
    asm volatile("ldmatrix.sync.aligned.m8n8.x4.shared.b16 {%0,%1,%2,%3}, [%4];" \
                 : "=r"(r0), "=r"(r1), "=r"(r2), "=r"(r3) : "r"(addr))

#define CPASYNC16(saddr, gaddr, sz)                                           \
    asm volatile("cp.async.cg.shared.global [%0], [%1], 16, %2;"              \
                 :: "r"(saddr), "l"(gaddr), "r"(sz) : "memory")

#define ROWB        144u
#define A_PLANE     18432u      /* 128 * 144 */
#define B_OFF       36864u      /* 2 * A_PLANE */
#define B_PLANE     9216u       /* 64 * 144 */
#define BUF_BYTES   55296u      /* B_OFF + 2*B_PLANE */
#define NSTAGE      2

__device__ __forceinline__ uint32_t smem_u32(const void* p) {
    uint32_t a;
    asm("{ .reg .u64 t; cvta.to.shared.u64 t, %1; cvt.u32.u64 %0, t; }"
        : "=r"(a) : "l"(p));
    return a;
}

template <int ACT, int SPLIT_OUT>
__global__ __launch_bounds__(256) void hmma_gemm(
    const __nv_bfloat16* __restrict__ Ah, const __nv_bfloat16* __restrict__ Al,
    const __nv_bfloat16* __restrict__ Bh, const __nv_bfloat16* __restrict__ Bl,
    const float* __restrict__ bias,
    float* __restrict__ Cf,
    __nv_bfloat16* __restrict__ Chi, __nv_bfloat16* __restrict__ Clo,
    int M, int N, int K)
{
    extern __shared__ char smem[];
    uint32_t sbase = smem_u32(smem);

    int tid = threadIdx.x;
    int wid = tid >> 5;
    int lane = tid & 31;
    int g = lane >> 2;
    int tg = lane & 3;
    int wm = wid >> 1;
    int wn = wid & 1;
    int m0 = blockIdx.x * 128;
    int n0 = blockIdx.y * 64;

    int lr = lane & 7;
    int lm01 = (lane >> 3) & 1;
    int lm23 = lane >> 4;

    float acc[2][4][4];
#pragma unroll
    for (int mi = 0; mi < 2; mi++)
#pragma unroll
        for (int ni = 0; ni < 4; ni++)
#pragma unroll
            for (int q = 0; q < 4; q++) acc[mi][ni][q] = 0.f;

    int nkc = (K + 63) >> 6;

    auto issue_chunk = [&](int c) {
        int kc = c << 6;
        uint32_t bufb = sbase + (uint32_t)(c & 1) * BUF_BYTES;
        // A: 2048 16B chunks (2 planes x 128 rows x 8 segs), 8/thread
#pragma unroll
        for (int r = 0; r < 8; ++r) {
            int i = tid + (r << 8);
            int plane = i >> 10;
            int row = (i >> 3) & 127;
            int seg = i & 7;
            int gm = m0 + row;
            int k = kc + seg * 8;
            const __nv_bfloat16* src = (plane ? Al : Ah) + (size_t)gm * K + k;
            uint32_t dst = bufb + (uint32_t)plane * A_PLANE + (uint32_t)row * ROWB
                           + (uint32_t)seg * 16u;
            uint32_t sz = (gm < M && k < K) ? 16u : 0u;
            CPASYNC16(dst, src, sz);
        }
        // B: 1024 16B chunks (2 planes x 64 rows x 8 segs), 4/thread
#pragma unroll
        for (int r = 0; r < 4; ++r) {
            int i = tid + (r << 8);
            int plane = i >> 9;
            int row = (i >> 3) & 63;
            int seg = i & 7;
            int gn = n0 + row;
            int k = kc + seg * 8;
            const __nv_bfloat16* src = (plane ? Bl : Bh) + (size_t)gn * K + k;
            uint32_t dst = bufb + B_OFF + (uint32_t)plane * B_PLANE
                           + (uint32_t)row * ROWB + (uint32_t)seg * 16u;
            uint32_t sz = (gn < N && k < K) ? 16u : 0u;
            CPASYNC16(dst, src, sz);
        }
        asm volatile("cp.async.commit_group;" ::: "memory");
    };

    issue_chunk(0);

    for (int c = 0; c < nkc; ++c) {
        if (c + 1 < nkc) {
            issue_chunk(c + 1);
            asm volatile("cp.async.wait_group 1;" ::: "memory");
        } else {
            asm volatile("cp.async.wait_group 0;" ::: "memory");
        }
        __syncthreads();

        uint32_t abase = sbase + (uint32_t)(c & 1) * BUF_BYTES;
        uint32_t bbase = abase + B_OFF;
#pragma unroll
        for (int ks = 0; ks < 64; ks += 16) {
            uint32_t ah[2][4], al[2][4], bh[4][2], bl[4][2];
#pragma unroll
            for (int mi = 0; mi < 2; mi++) {
                uint32_t row = (uint32_t)(wm * 32 + mi * 16 + lm01 * 8 + lr);
                uint32_t col = (uint32_t)(ks + lm23 * 8);
                uint32_t off = row * ROWB + col * 2u;
                LDSM4(ah[mi][0], ah[mi][1], ah[mi][2], ah[mi][3], abase + off);
                LDSM4(al[mi][0], al[mi][1], al[mi][2], al[mi][3],
                      abase + A_PLANE + off);
            }
#pragma unroll
            for (int ng = 0; ng < 2; ng++) {
                uint32_t row = (uint32_t)(wn * 32 + ng * 16 + lm23 * 8 + lr);
                uint32_t col = (uint32_t)(ks + lm01 * 8);
                uint32_t off = row * ROWB + col * 2u;
                LDSM4(bh[2 * ng][0], bh[2 * ng][1], bh[2 * ng + 1][0],
                      bh[2 * ng + 1][1], bbase + off);
                LDSM4(bl[2 * ng][0], bl[2 * ng][1], bl[2 * ng + 1][0],
                      bl[2 * ng + 1][1], bbase + B_PLANE + off);
            }
            // product-major: 8 independent MMAs per pass
#pragma unroll
            for (int mi = 0; mi < 2; mi++)
#pragma unroll
                for (int ni = 0; ni < 4; ni++)
                    MMA16816(acc[mi][ni], ah[mi], bh[ni]);
#pragma unroll
            for (int mi = 0; mi < 2; mi++)
#pragma unroll
                for (int ni = 0; ni < 4; ni++)
                    MMA16816(acc[mi][ni], ah[mi], bl[ni]);
#pragma unroll
            for (int mi = 0; mi < 2; mi++)
#pragma unroll
                for (int ni = 0; ni < 4; ni++)
                    MMA16816(acc[mi][ni], al[mi], bh[ni]);
        }
        __syncthreads();
    }

    // ---- epilogue ----
#pragma unroll
    for (int mi = 0; mi < 2; mi++) {
#pragma unroll
        for (int ni = 0; ni < 4; ni++) {
#pragma unroll
            for (int h = 0; h < 2; h++) {
                int gm = m0 + wm * 32 + mi * 16 + g + h * 8;
                if (gm >= M) continue;
#pragma unroll
                for (int q = 0; q < 2; q++) {
                    int gn = n0 + wn * 32 + ni * 8 + tg * 2 + q;
                    if (gn >= N) continue;
                    float v = acc[mi][ni][h * 2 + q];
                    if (bias) v += bias[gn];
                    if (ACT == 1) v = v / (1.f + expf(-v));
                    if (SPLIT_OUT == 1) {
                        __nv_bfloat16 hh = __float2bfloat16(v);
                        Chi[(size_t)gm * N + gn] = hh;
                        Clo[(size_t)gm * N + gn] =
                            __float2bfloat16(v - __bfloat162float(hh));
                    } else {
                        Cf[(size_t)gm * N + gn] = v;
                    }
                }
            }
        }
    }
}

// ---------------- residual + LayerNorm (shuffle reductions) ----------------
__global__ void ln_kernel(const float* __restrict__ F, const float* __restrict__ h2,
                          const float* __restrict__ gamma, const float* __restrict__ beta,
                          float* __restrict__ out) {
    __shared__ float wred[8];
    int n = blockIdx.x;
    int tid = threadIdx.x;
    int lane = tid & 31;
    int wid = tid >> 5;
    float x = (tid < DD) ? (F[n * DD + tid] + h2[n * DD + tid]) : 0.f;

    float s = x;
#pragma unroll
    for (int o = 16; o > 0; o >>= 1) s += __shfl_xor_sync(0xFFFFFFFFu, s, o);
    if (lane == 0) wred[wid] = s;
    __syncthreads();
    float mu = 0.f;
#pragma unroll
    for (int i = 0; i < 8; i++) mu += wred[i];
    mu *= (1.f / DD);
    __syncthreads();

    float xc = (tid < DD) ? (x - mu) : 0.f;
    float s2 = xc * xc;
#pragma unroll
    for (int o = 16; o > 0; o >>= 1) s2 += __shfl_xor_sync(0xFFFFFFFFu, s2, o);
    if (lane == 0) wred[wid] = s2;
    __syncthreads();
    float var = 0.f;
#pragma unroll
    for (int i = 0; i < 8; i++) var += wred[i];
    var *= (1.f / DD);
    float r = rsqrtf(var + 1e-5f);
    if (tid < DD)
        out[n * DD + tid] = xc * r * gamma[tid] + beta[tid];
}

// ---------------- launcher ----------------
extern "C" void kernel_launch(void* const* d_in, const int* in_sizes, int n_in,
                              void* d_out, int out_size) {
    const float* features = (const float*)d_in[0];
    const int*   ei       = (const int*)d_in[1];
    const float* Wmsg     = (const float*)d_in[2];
    const float* W1       = (const float*)d_in[3];
    const float* b1       = (const float*)d_in[4];
    const float* W2       = (const float*)d_in[5];
    const float* b2       = (const float*)d_in[6];
    const float* gamma    = (const float*)d_in[7];
    const float* beta     = (const float*)d_in[8];
    const int*   Iv       = (const int*)d_in[9];
    const int*   Jv       = (const int*)d_in[10];
    const int*   Kv       = (const int*)d_in[11];
    const float* Cv       = (const float*)d_in[12];
    float* out = (float*)d_out;

    int N   = in_sizes[0] / DD;
    int E   = in_sizes[1] / 2;
    int nnz = in_sizes[9];

    float *p_proj, *p_S, *p_h2;
    __nv_bfloat16 *p_fhi, *p_flo, *p_agghi, *p_agglo, *p_hidhi, *p_hidlo;
    __nv_bfloat16 *p_wmhi, *p_wmlo, *p_w1hi, *p_w1lo, *p_w2hi, *p_w2lo;
    cudaGetSymbolAddress((void**)&p_proj,  g_proj);
    cudaGetSymbolAddress((void**)&p_S,     g_S);
    cudaGetSymbolAddress((void**)&p_h2,    g_h2);
    cudaGetSymbolAddress((void**)&p_fhi,   g_fhi);
    cudaGetSymbolAddress((void**)&p_flo,   g_flo);
    cudaGetSymbolAddress((void**)&p_agghi, g_agghi);
    cudaGetSymbolAddress((void**)&p_agglo, g_agglo);
    cudaGetSymbolAddress((void**)&p_hidhi, g_hidhi);
    cudaGetSymbolAddress((void**)&p_hidlo, g_hidlo);
    cudaGetSymbolAddress((void**)&p_wmhi,  g_wmhi);
    cudaGetSymbolAddress((void**)&p_wmlo,  g_wmlo);
    cudaGetSymbolAddress((void**)&p_w1hi,  g_w1hi);
    cudaGetSymbolAddress((void**)&p_w1lo,  g_w1lo);
    cudaGetSymbolAddress((void**)&p_w2hi,  g_w2hi);
    cudaGetSymbolAddress((void**)&p_w2lo,  g_w2lo);

    const int SMEM_SZ = NSTAGE * 55296;
    cudaFuncSetAttribute(hmma_gemm<0, 0>, cudaFuncAttributeMaxDynamicSharedMemorySize, SMEM_SZ);
    cudaFuncSetAttribute(hmma_gemm<1, 1>, cudaFuncAttributeMaxDynamicSharedMemorySize, SMEM_SZ);

    // #1: features split + zero S
    prep_feat_kernel<<<512, 256>>>(features, p_fhi, p_flo, p_S, N * DD);
    // #2: weight splits
    prep_w_kernel<<<256, 256>>>(Wmsg, W1, W2, p_wmhi, p_wmlo,
                                p_w1hi, p_w1lo, p_w2hi, p_w2lo);
    // #3: deterministic parallel CSR
    build_csr_fast<<<(nnz + 255) / 256, 256>>>(Iv, Jv, Kv, Cv, nnz);

    int mtiles = (N + 127) / 128;

    // #4 (profiled): proj = features @ Wmsg^T
    hmma_gemm<0, 0><<<dim3(mtiles, (DD + 63) / 64), 256, SMEM_SZ>>>(
        p_fhi, p_flo, p_wmhi, p_wmlo, nullptr, p_proj, nullptr, nullptr, N, DD, DD);

    // #5: S[tgt] += proj[src]
    scatter_edges_kernel<<<(E * 64 + 255) / 256, 256>>>(ei, p_proj, p_S, E);

    // #6: agg = bracket(S, features), pre-split
    bracket_kernel<<<N, 256>>>(p_S, features, p_agghi, p_agglo);

    // #7: hidden = silu(agg @ W1^T + b1), pre-split
    hmma_gemm<1, 1><<<dim3(mtiles, (HH + 63) / 64), 256, SMEM_SZ>>>(
        p_agghi, p_agglo, p_w1hi, p_w1lo, b1, nullptr, p_hidhi, p_hidlo, N, HH, DD);

    // #8: h2 = hidden @ W2^T + b2
    hmma_gemm<0, 0><<<dim3(mtiles, (DD + 63) / 64), 256, SMEM_SZ>>>(
        p_hidhi, p_hidlo, p_w2hi, p_w2lo, b2, p_h2, nullptr, nullptr, N, DD, HH);

    // #9: out = LayerNorm(features + h2)
    ln_kernel<<<N, 256>>>(features, p_h2, gamma, beta, out);
}